// round 12
// baseline (speedup 1.0000x reference)
#include <cuda_runtime.h>
#include <cuda_fp16.h>
#include <cstdint>

#define NMAX 100000
#define EMAX 1600000
#define HID 128
#define GNUM 64
#define RELN 51
#define NEG 0.2f
#define EG 592   // edge-pass grid (4 * 148)

// ---------------- scratch ----------------
__device__ float  g_h[(size_t)NMAX * HID];
__device__ __half g_xlh[(size_t)NMAX * HID];   // fp16 gather tables (edge-only consumers)
__device__ __half g_xrh[(size_t)NMAX * HID];
__device__ float  g_agg[(size_t)NMAX * HID];
__device__ float  g_part[EG * 256];
__device__ float  g_scale[HID];
__device__ float  g_shift[HID];
__device__ float  g_pool[GNUM * HID];
__device__ int    g_pcnt[GNUM];
__device__ int    g_deg[NMAX];        // MUST be zero at entry (zero-init + tail kernel)
__device__ int    g_rowptr[NMAX + 1];
__device__ int    g_rp2[NMAX + 1];
__device__ int    g_scan[NMAX];
__device__ int    g_bsum[128];
__device__ int    g_csr[EMAX];

// ---------------- tf32 helpers ----------------
__device__ __forceinline__ uint32_t f2tf32(float x) {
    uint32_t r;
    asm("cvt.rna.tf32.f32 %0, %1;" : "=r"(r) : "f"(x));
    return r;
}
__device__ __forceinline__ void mma_tf32(float d[4], const uint32_t a[4],
                                         const uint32_t b[2]) {
    asm volatile(
        "mma.sync.aligned.m16n8k8.row.col.f32.tf32.tf32.f32 "
        "{%0,%1,%2,%3}, {%4,%5,%6,%7}, {%8,%9}, {%0,%1,%2,%3};"
        : "+f"(d[0]), "+f"(d[1]), "+f"(d[2]), "+f"(d[3])
        : "r"(a[0]), "r"(a[1]), "r"(a[2]), "r"(a[3]), "r"(b[0]), "r"(b[1]));
}

// ---------------- CSR build ----------------
__global__ void k_hist(const int* __restrict__ dst, int e) {
    int i = blockIdx.x * blockDim.x + threadIdx.x;
    if (i < e) atomicAdd(&g_deg[dst[i]], 1);
}
__global__ void k_scan1(int n) {
    __shared__ int sh[1024];
    int t = threadIdx.x;
    int i = blockIdx.x * 1024 + t;
    int v = (i < n) ? g_deg[i] : 0;
    sh[t] = v;
    __syncthreads();
    for (int off = 1; off < 1024; off <<= 1) {
        int x = (t >= off) ? sh[t - off] : 0;
        __syncthreads();
        sh[t] += x;
        __syncthreads();
    }
    if (i < n) g_scan[i] = sh[t];
    if (t == 1023) g_bsum[blockIdx.x] = sh[1023];
}
__global__ void k_scan23(int n, int nb) {
    __shared__ int bs[128];
    int t = threadIdx.x;
    if (t < nb) bs[t] = g_bsum[t];
    __syncthreads();
    int i = blockIdx.x * blockDim.x + t;
    if (i >= n) return;
    int b = i >> 10;
    int off = 0;
    for (int j = 0; j < b; j++) off += bs[j];
    int v = g_scan[i] + off;
    g_rowptr[i + 1] = v;
    g_rp2[i + 1] = v;
    if (i == 0) { g_rowptr[0] = 0; g_rp2[0] = 0; }
}
__global__ void k_scatter(const int* __restrict__ src,
                          const int* __restrict__ dst,
                          const int* __restrict__ rel, int e) {
    int i = blockIdx.x * blockDim.x + threadIdx.x;
    if (i >= e) return;
    int d = dst[i];
    int pos = atomicAdd(&g_rp2[d], 1);
    g_csr[pos] = src[i] | (rel[i] << 20);
}
__global__ void k_zero_tail(int n) {
    int i = blockIdx.x * blockDim.x + threadIdx.x;
    if (i < n) g_deg[i] = 0;
}

// ---------------- epilogue store helper: 2 fp32 -> half2 ----------------
__device__ __forceinline__ void store_h2(__half* Y, size_t idx, float a, float b) {
    *(__half2*)&Y[idx] = __float22half2_rn(make_float2(a, b));
}

// ---------------- layer-0 fused dual GEMM with in-place feature build ----------------
__global__ void __launch_bounds__(256, 2)
k_gemm_l0(const int* __restrict__ tok, const float* __restrict__ bbox,
          const float* __restrict__ temb,
          const float* __restrict__ bW, const float* __restrict__ bb,
          const float* __restrict__ Wl, const float* __restrict__ bl,
          const float* __restrict__ Wr, const float* __restrict__ br,
          __half* __restrict__ Yl, __half* __restrict__ Yr, int n) {
    const int IND = 288, KT = 32;
    __shared__ uint32_t Xs[KT][72];
    __shared__ uint32_t Wsm[KT][264];
    int t = threadIdx.x, lane = t & 31, wid = t >> 5;
    int grp = lane >> 2, thc = lane & 3;
    int mw = wid & 1, nw = wid >> 1;
    int rowbase = blockIdx.x * 64;

    float d[2][8][4];
#pragma unroll
    for (int mi = 0; mi < 2; mi++)
#pragma unroll
        for (int nj = 0; nj < 8; nj++)
#pragma unroll
            for (int q = 0; q < 4; q++) d[mi][nj][q] = 0.f;

    int srow = t >> 2;
    int sks = (t & 3) * 8;
    int grow = rowbase + srow;
    bool rok = grow < n;
    const float* trow = &temb[(size_t)(rok ? tok[grow] : 0) * 256];
    float4 bx = make_float4(0.f, 0.f, 0.f, 0.f);
    if (rok) bx = *(const float4*)&bbox[grow * 4];

    for (int kt = 0; kt < IND; kt += KT) {
        if (kt < 256) {
#pragma unroll
            for (int q = 0; q < 2; q++) {
                float4 v = make_float4(0.f, 0.f, 0.f, 0.f);
                if (rok) v = *(const float4*)&trow[kt + sks + q * 4];
                Xs[sks + q * 4 + 0][srow] = f2tf32(v.x);
                Xs[sks + q * 4 + 1][srow] = f2tf32(v.y);
                Xs[sks + q * 4 + 2][srow] = f2tf32(v.z);
                Xs[sks + q * 4 + 3][srow] = f2tf32(v.w);
            }
        } else {
#pragma unroll
            for (int q = 0; q < 8; q++) {
                int j = sks + q;
                float v = 0.f;
                if (rok)
                    v = bb[j] + bx.x * bW[j] + bx.y * bW[32 + j] +
                        bx.z * bW[64 + j] + bx.w * bW[96 + j];
                Xs[j][srow] = f2tf32(v);
            }
        }
#pragma unroll
        for (int j = 0; j < 8; j++) {
            int id = j * 256 + t;
            int krow = id >> 6, c4 = (id & 63) * 4;
            float4 wv;
            if (c4 < 128) wv = *(const float4*)&Wl[(size_t)(kt + krow) * 128 + c4];
            else          wv = *(const float4*)&Wr[(size_t)(kt + krow) * 128 + (c4 - 128)];
            uint4 u;
            u.x = f2tf32(wv.x); u.y = f2tf32(wv.y);
            u.z = f2tf32(wv.z); u.w = f2tf32(wv.w);
            *(uint4*)&Wsm[krow][c4] = u;
        }
        __syncthreads();
#pragma unroll
        for (int kk = 0; kk < KT; kk += 8) {
            uint32_t a[2][4];
#pragma unroll
            for (int mi = 0; mi < 2; mi++) {
                int r = mw * 32 + mi * 16 + grp;
                a[mi][0] = Xs[kk + thc][r];
                a[mi][1] = Xs[kk + thc][r + 8];
                a[mi][2] = Xs[kk + thc + 4][r];
                a[mi][3] = Xs[kk + thc + 4][r + 8];
            }
            uint32_t b[8][2];
#pragma unroll
            for (int nj = 0; nj < 8; nj++) {
                int c = nw * 64 + nj * 8 + grp;
                b[nj][0] = Wsm[kk + thc][c];
                b[nj][1] = Wsm[kk + thc + 4][c];
            }
#pragma unroll
            for (int mi = 0; mi < 2; mi++)
#pragma unroll
                for (int nj = 0; nj < 8; nj++)
                    mma_tf32(d[mi][nj], a[mi], b[nj]);
        }
        __syncthreads();
    }
#pragma unroll
    for (int mi = 0; mi < 2; mi++) {
        int r0 = rowbase + mw * 32 + mi * 16 + grp;
#pragma unroll
        for (int nj = 0; nj < 8; nj++) {
            int colg = nw * 64 + nj * 8 + 2 * thc;
            const float* B = (colg < 128) ? bl : br;
            __half* Y = (colg < 128) ? Yl : Yr;
            int col = colg & 127;
            float2 bv = *(const float2*)&B[col];
            if (r0 < n)
                store_h2(Y, (size_t)r0 * 128 + col, d[mi][nj][0] + bv.x, d[mi][nj][1] + bv.y);
            if (r0 + 8 < n)
                store_h2(Y, (size_t)(r0 + 8) * 128 + col, d[mi][nj][2] + bv.x, d[mi][nj][3] + bv.y);
        }
    }
}

// ---------------- layers 1-2 GEMM with fused BN-apply in X staging ----------------
__global__ void __launch_bounds__(256, 2)
k_gemm_tc2f(const float* __restrict__ Wl, const float* __restrict__ bl,
            const float* __restrict__ Wr, const float* __restrict__ br,
            __half* __restrict__ Yl, __half* __restrict__ Yr, int n, int res) {
    const int IND = 128, KT = 32;
    __shared__ uint32_t Xs[KT][72];
    __shared__ uint32_t Wsm[KT][264];
    int t = threadIdx.x, lane = t & 31, wid = t >> 5;
    int grp = lane >> 2, thc = lane & 3;
    int mw = wid & 1, nw = wid >> 1;
    int rowbase = blockIdx.x * 64;

    float d[2][8][4];
#pragma unroll
    for (int mi = 0; mi < 2; mi++)
#pragma unroll
        for (int nj = 0; nj < 8; nj++)
#pragma unroll
            for (int q = 0; q < 4; q++) d[mi][nj][q] = 0.f;

    int srow = t >> 2;
    int sks = (t & 3) * 8;
    int grow = rowbase + srow;
    bool rok = grow < n;
    size_t rowoff = (size_t)(rok ? grow : 0) * 128;

    for (int kt = 0; kt < IND; kt += KT) {
#pragma unroll
        for (int q = 0; q < 2; q++) {
            int kb = kt + sks + q * 4;
            float4 x = make_float4(0.f, 0.f, 0.f, 0.f);
            if (rok) {
                float4 v = *(const float4*)&g_agg[rowoff + kb];
                float4 s4 = *(const float4*)&g_scale[kb];
                float4 f4 = *(const float4*)&g_shift[kb];
                x.x = s4.x * v.x + f4.x;
                x.y = s4.y * v.y + f4.y;
                x.z = s4.z * v.z + f4.z;
                x.w = s4.w * v.w + f4.w;
                if (res) {
                    float4 hp = *(const float4*)&g_h[rowoff + kb];
                    x.x += hp.x; x.y += hp.y; x.z += hp.z; x.w += hp.w;
                }
                *(float4*)&g_h[rowoff + kb] = x;
            }
            Xs[sks + q * 4 + 0][srow] = f2tf32(x.x);
            Xs[sks + q * 4 + 1][srow] = f2tf32(x.y);
            Xs[sks + q * 4 + 2][srow] = f2tf32(x.z);
            Xs[sks + q * 4 + 3][srow] = f2tf32(x.w);
        }
#pragma unroll
        for (int j = 0; j < 8; j++) {
            int id = j * 256 + t;
            int krow = id >> 6, c4 = (id & 63) * 4;
            float4 wv;
            if (c4 < 128) wv = *(const float4*)&Wl[(size_t)(kt + krow) * 128 + c4];
            else          wv = *(const float4*)&Wr[(size_t)(kt + krow) * 128 + (c4 - 128)];
            uint4 u;
            u.x = f2tf32(wv.x); u.y = f2tf32(wv.y);
            u.z = f2tf32(wv.z); u.w = f2tf32(wv.w);
            *(uint4*)&Wsm[krow][c4] = u;
        }
        __syncthreads();
#pragma unroll
        for (int kk = 0; kk < KT; kk += 8) {
            uint32_t a[2][4];
#pragma unroll
            for (int mi = 0; mi < 2; mi++) {
                int r = mw * 32 + mi * 16 + grp;
                a[mi][0] = Xs[kk + thc][r];
                a[mi][1] = Xs[kk + thc][r + 8];
                a[mi][2] = Xs[kk + thc + 4][r];
                a[mi][3] = Xs[kk + thc + 4][r + 8];
            }
            uint32_t b[8][2];
#pragma unroll
            for (int nj = 0; nj < 8; nj++) {
                int c = nw * 64 + nj * 8 + grp;
                b[nj][0] = Wsm[kk + thc][c];
                b[nj][1] = Wsm[kk + thc + 4][c];
            }
#pragma unroll
            for (int mi = 0; mi < 2; mi++)
#pragma unroll
                for (int nj = 0; nj < 8; nj++)
                    mma_tf32(d[mi][nj], a[mi], b[nj]);
        }
        __syncthreads();
    }
#pragma unroll
    for (int mi = 0; mi < 2; mi++) {
        int r0 = rowbase + mw * 32 + mi * 16 + grp;
#pragma unroll
        for (int nj = 0; nj < 8; nj++) {
            int colg = nw * 64 + nj * 8 + 2 * thc;
            const float* B = (colg < 128) ? bl : br;
            __half* Y = (colg < 128) ? Yl : Yr;
            int col = colg & 127;
            float2 bv = *(const float2*)&B[col];
            if (r0 < n)
                store_h2(Y, (size_t)r0 * 128 + col, d[mi][nj][0] + bv.x, d[mi][nj][1] + bv.y);
            if (r0 + 8 < n)
                store_h2(Y, (size_t)(r0 + 8) * 128 + col, d[mi][nj][2] + bv.x, d[mi][nj][3] + bv.y);
        }
    }
}

// ---------------- fp16 gather -> float4 ----------------
__device__ __forceinline__ float4 load_h4(const __half* p) {
    uint2 raw = *(const uint2*)p;   // 8B load: 4 halves
    __half2 h0 = *(__half2*)&raw.x;
    __half2 h1 = *(__half2*)&raw.y;
    float2 f0 = __half22float2(h0);
    float2 f1 = __half22float2(h1);
    return make_float4(f0.x, f0.y, f1.x, f1.y);
}

// ---------------- fused edge pass (unroll-2, fp16 gathers) ----------------
__global__ void __launch_bounds__(256) k_edge(const float* __restrict__ att,
                                              const float* __restrict__ bias,
                                              const float* __restrict__ relemb,
                                              const float* __restrict__ We, int n) {
    __shared__ float ee[RELN * HID];
    __shared__ float red[8][32][8];
    int t = threadIdx.x;
    for (int i = t; i < RELN * HID; i += 256) {
        int r = i >> 7, j = i & 127;
        float s = 0.f;
#pragma unroll
        for (int c = 0; c < 16; c++) s += relemb[r * 16 + c] * We[c * 128 + j];
        ee[i] = s;
    }
    __syncthreads();
    int lane = t & 31, wid = t >> 5;
    float4 av = *(const float4*)&att[(lane >> 2) * 16 + (lane & 3) * 4];
    float4 bv = *(const float4*)&bias[lane * 4];
    float ps0 = 0.f, ps1 = 0.f, ps2 = 0.f, ps3 = 0.f;
    float pq0 = 0.f, pq1 = 0.f, pq2 = 0.f, pq3 = 0.f;

    for (int node = blockIdx.x * 8 + wid; node < n; node += EG * 8) {
        int r0 = g_rowptr[node], r1 = g_rowptr[node + 1];
        float4 xr = load_h4(&g_xrh[(size_t)node * 128 + lane * 4]);
        float4 acc = {0.f, 0.f, 0.f, 0.f};
        float den = 0.f;
        int i = r0;
        for (; i + 2 <= r1; i += 2) {
            int pe0 = g_csr[i], pe1 = g_csr[i + 1];
            float4 xl0 = load_h4(&g_xlh[(size_t)(pe0 & 0xFFFFF) * 128 + lane * 4]);
            float4 ev0 = *(const float4*)&ee[(pe0 >> 20) * 128 + lane * 4];
            float4 xl1 = load_h4(&g_xlh[(size_t)(pe1 & 0xFFFFF) * 128 + lane * 4]);
            float4 ev1 = *(const float4*)&ee[(pe1 >> 20) * 128 + lane * 4];
            float m, s0, s1;
            m = xl0.x + xr.x + ev0.x; m = m > 0.f ? m : NEG * m; s0 = m * av.x;
            m = xl0.y + xr.y + ev0.y; m = m > 0.f ? m : NEG * m; s0 += m * av.y;
            m = xl0.z + xr.z + ev0.z; m = m > 0.f ? m : NEG * m; s0 += m * av.z;
            m = xl0.w + xr.w + ev0.w; m = m > 0.f ? m : NEG * m; s0 += m * av.w;
            m = xl1.x + xr.x + ev1.x; m = m > 0.f ? m : NEG * m; s1 = m * av.x;
            m = xl1.y + xr.y + ev1.y; m = m > 0.f ? m : NEG * m; s1 += m * av.y;
            m = xl1.z + xr.z + ev1.z; m = m > 0.f ? m : NEG * m; s1 += m * av.z;
            m = xl1.w + xr.w + ev1.w; m = m > 0.f ? m : NEG * m; s1 += m * av.w;
            s0 += __shfl_xor_sync(0xffffffffu, s0, 1);
            s0 += __shfl_xor_sync(0xffffffffu, s0, 2);
            s1 += __shfl_xor_sync(0xffffffffu, s1, 1);
            s1 += __shfl_xor_sync(0xffffffffu, s1, 2);
            float p0 = __expf(s0), p1 = __expf(s1);
            den += p0 + p1;
            acc.x += p0 * xl0.x + p1 * xl1.x;
            acc.y += p0 * xl0.y + p1 * xl1.y;
            acc.z += p0 * xl0.z + p1 * xl1.z;
            acc.w += p0 * xl0.w + p1 * xl1.w;
        }
        if (i < r1) {
            int pe0 = g_csr[i];
            float4 xl0 = load_h4(&g_xlh[(size_t)(pe0 & 0xFFFFF) * 128 + lane * 4]);
            float4 ev0 = *(const float4*)&ee[(pe0 >> 20) * 128 + lane * 4];
            float m, s0;
            m = xl0.x + xr.x + ev0.x; m = m > 0.f ? m : NEG * m; s0 = m * av.x;
            m = xl0.y + xr.y + ev0.y; m = m > 0.f ? m : NEG * m; s0 += m * av.y;
            m = xl0.z + xr.z + ev0.z; m = m > 0.f ? m : NEG * m; s0 += m * av.z;
            m = xl0.w + xr.w + ev0.w; m = m > 0.f ? m : NEG * m; s0 += m * av.w;
            s0 += __shfl_xor_sync(0xffffffffu, s0, 1);
            s0 += __shfl_xor_sync(0xffffffffu, s0, 2);
            float p0 = __expf(s0);
            den += p0;
            acc.x += p0 * xl0.x;
            acc.y += p0 * xl0.y;
            acc.z += p0 * xl0.z;
            acc.w += p0 * xl0.w;
        }
        float inv = __frcp_rn(fmaxf(den, 1e-16f));
        float4 o;
        o.x = fmaxf(acc.x * inv + bv.x, 0.f);
        o.y = fmaxf(acc.y * inv + bv.y, 0.f);
        o.z = fmaxf(acc.z * inv + bv.z, 0.f);
        o.w = fmaxf(acc.w * inv + bv.w, 0.f);
        *(float4*)&g_agg[(size_t)node * 128 + lane * 4] = o;
        ps0 += o.x; ps1 += o.y; ps2 += o.z; ps3 += o.w;
        pq0 += o.x * o.x; pq1 += o.y * o.y; pq2 += o.z * o.z; pq3 += o.w * o.w;
    }
    red[wid][lane][0] = ps0; red[wid][lane][1] = ps1;
    red[wid][lane][2] = ps2; red[wid][lane][3] = ps3;
    red[wid][lane][4] = pq0; red[wid][lane][5] = pq1;
    red[wid][lane][6] = pq2; red[wid][lane][7] = pq3;
    __syncthreads();
    int stat = t >> 7, ch = t & 127;
    int ln = ch >> 2, j = ch & 3;
    float s = 0.f;
#pragma unroll
    for (int w = 0; w < 8; w++) s += red[w][ln][stat * 4 + j];
    g_part[blockIdx.x * 256 + t] = s;
}

// ---------------- BN finalize ----------------
__global__ void k_bnr2(const float* __restrict__ gamma,
                       const float* __restrict__ beta, int n) {
    __shared__ float sh[256];
    int t = threadIdx.x;
    float s = 0.f;
#pragma unroll 4
    for (int b = 0; b < EG; b++) s += g_part[b * 256 + t];
    sh[t] = s;
    __syncthreads();
    if (t < 128) {
        float inv_n = 1.0f / (float)n;
        float mu = sh[t] * inv_n;
        float var = sh[128 + t] * inv_n - mu * mu;
        float rs = rsqrtf(var + 1e-5f);
        float sc = gamma[t] * rs;
        g_scale[t] = sc;
        g_shift[t] = beta[t] - mu * sc;
    }
}

// ---------------- pooling (fused with final BN apply + residual) ----------------
__global__ void k_pool_zero() {
    int i = blockIdx.x * blockDim.x + threadIdx.x;
    if (i < GNUM * HID) g_pool[i] = 0.f;
    if (i < GNUM) g_pcnt[i] = 0;
}
__global__ void k_pool_apply(const int* __restrict__ batch, int n) {
    const int CHUNK = 256;
    int t = threadIdx.x;
    float sc = g_scale[t], sf = g_shift[t];
    int r0 = blockIdx.x * CHUNK;
    int rend = min(r0 + CHUNK, n);
    float a = 0.f;
    int lc = 0, cur = -1;
    for (int r = r0; r < rend; r++) {
        int g = batch[r];
        if (g != cur) {
            if (cur >= 0) {
                atomicAdd(&g_pool[cur * 128 + t], a);
                if (t == 0) atomicAdd(&g_pcnt[cur], lc);
            }
            a = 0.f;
            lc = 0;
            cur = g;
        }
        a += g_h[(size_t)r * 128 + t] + sc * g_agg[(size_t)r * 128 + t] + sf;
        lc++;
    }
    if (cur >= 0) {
        atomicAdd(&g_pool[cur * 128 + t], a);
        if (t == 0) atomicAdd(&g_pcnt[cur], lc);
    }
}
__global__ void k_pool_fin(float* __restrict__ out) {
    int i = blockIdx.x * blockDim.x + threadIdx.x;
    if (i >= GNUM * HID) return;
    out[i] = g_pool[i] / fmaxf((float)g_pcnt[i >> 7], 1.0f);
}

// ---------------- host launch ----------------
extern "C" void kernel_launch(void* const* d_in, const int* in_sizes, int n_in,
                              void* d_out, int out_size) {
    const int* tok = (const int*)d_in[0];
    const float* bbox = (const float*)d_in[1];
    const int* ei = (const int*)d_in[2];
    const int* eattr = (const int*)d_in[3];
    const int* batch = (const int*)d_in[4];
    const float* temb = (const float*)d_in[5];
    const float* bW = (const float*)d_in[6];
    const float* bb = (const float*)d_in[7];
    const float* relemb = (const float*)d_in[8];
    const float* Wl0 = (const float*)d_in[9];
    const float* bl0 = (const float*)d_in[10];
    const float* Wr0 = (const float*)d_in[11];
    const float* br0 = (const float*)d_in[12];
    const float* We0 = (const float*)d_in[13];
    const float* att0 = (const float*)d_in[14];
    const float* bias0 = (const float*)d_in[15];
    const float* gamma0 = (const float*)d_in[16];
    const float* beta0 = (const float*)d_in[17];
    const float* WlS = (const float*)d_in[18];
    const float* blS = (const float*)d_in[19];
    const float* WrS = (const float*)d_in[20];
    const float* brS = (const float*)d_in[21];
    const float* WeS = (const float*)d_in[22];
    const float* attS = (const float*)d_in[23];
    const float* biasS = (const float*)d_in[24];
    const float* gammaS = (const float*)d_in[25];
    const float* betaS = (const float*)d_in[26];

    int n = in_sizes[0];
    int e = in_sizes[3];
    const int* src = ei;
    const int* dst = ei + e;

    __half *p_xl, *p_xr;
    cudaGetSymbolAddress((void**)&p_xl, g_xlh);
    cudaGetSymbolAddress((void**)&p_xr, g_xrh);

    int gN = (n + 255) / 256;
    int gE = (e + 255) / 256;
    int nbScan = (n + 1023) / 1024;
    int gemmGrid = (n + 63) / 64;

    k_hist<<<gE, 256>>>(dst, e);
    k_scan1<<<nbScan, 1024>>>(n);
    k_scan23<<<gN, 256>>>(n, nbScan);
    // idx 3: layer-0 GEMM (CSR-independent) -> ncu sample window lands here
    k_gemm_l0<<<gemmGrid, 256>>>(tok, bbox, temb, bW, bb,
                                 Wl0, bl0, Wr0, br0, p_xl, p_xr, n);
    k_scatter<<<gE, 256>>>(src, dst, eattr, e);

    for (int l = 0; l < 3; l++) {
        const float *Wl, *bl, *Wr, *br, *We, *att, *bias, *gamma, *beta;
        if (l == 0) {
            Wl = Wl0; bl = bl0; Wr = Wr0; br = br0; We = We0;
            att = att0; bias = bias0; gamma = gamma0; beta = beta0;
        } else {
            int j = l - 1;
            Wl = WlS + (size_t)j * 128 * 128; bl = blS + j * 128;
            Wr = WrS + (size_t)j * 128 * 128; br = brS + j * 128;
            We = WeS + (size_t)j * 16 * 128;
            att = attS + j * 128;
            bias = biasS + j * 128; gamma = gammaS + j * 128; beta = betaS + j * 128;
        }
        if (l > 0) {
            k_gemm_tc2f<<<gemmGrid, 256>>>(Wl, bl, Wr, br, p_xl, p_xr, n, l - 1);
        }
        k_edge<<<EG, 256>>>(att, bias, relemb, We, n);
        k_bnr2<<<1, 256>>>(gamma, beta, n);
    }

    k_pool_zero<<<(GNUM * HID + 255) / 256, 256>>>();
    k_pool_apply<<<(n + 255) / 256, 128>>>(batch, n);
    k_pool_fin<<<(GNUM * HID + 255) / 256, 256>>>((float*)d_out);
    k_zero_tail<<<gN, 256>>>(n);
}

// round 13
// speedup vs baseline: 1.0795x; 1.0795x over previous
#include <cuda_runtime.h>
#include <cstdint>

#define NMAX 100000
#define EMAX 1600000
#define HID 128
#define GNUM 64
#define RELN 51
#define NEG 0.2f
#define EG 592   // edge-pass grid (4 * 148)

// ---------------- scratch ----------------
__device__ float g_h[(size_t)NMAX * HID];
__device__ float g_xl[(size_t)NMAX * HID];
__device__ float g_xr[(size_t)NMAX * HID];
__device__ float g_agg[(size_t)NMAX * HID];
__device__ float g_sum[256];          // BN sums/sumsqs; MUST be zero at edge launch (zero-init + bnr2 self-zero)
__device__ float g_scale[HID];
__device__ float g_shift[HID];
__device__ float g_pool[GNUM * HID];  // MUST be zero at pool launch (zero-init + tail zero)
__device__ int   g_pcnt[GNUM];
__device__ int   g_deg[NMAX];         // MUST be zero at entry (zero-init + tail zero)
__device__ int   g_rowptr[NMAX + 1];
__device__ int   g_rp2[NMAX + 1];
__device__ int   g_scan[NMAX];
__device__ int   g_bsum[128];
__device__ int   g_csr[EMAX];

// ---------------- tf32 helpers ----------------
__device__ __forceinline__ uint32_t f2tf32(float x) {
    uint32_t r;
    asm("cvt.rna.tf32.f32 %0, %1;" : "=r"(r) : "f"(x));
    return r;
}
__device__ __forceinline__ void mma_tf32(float d[4], const uint32_t a[4],
                                         const uint32_t b[2]) {
    asm volatile(
        "mma.sync.aligned.m16n8k8.row.col.f32.tf32.tf32.f32 "
        "{%0,%1,%2,%3}, {%4,%5,%6,%7}, {%8,%9}, {%0,%1,%2,%3};"
        : "+f"(d[0]), "+f"(d[1]), "+f"(d[2]), "+f"(d[3])
        : "r"(a[0]), "r"(a[1]), "r"(a[2]), "r"(a[3]), "r"(b[0]), "r"(b[1]));
}

// ---------------- CSR build ----------------
__global__ void k_hist(const int* __restrict__ dst, int e) {
    int i = blockIdx.x * blockDim.x + threadIdx.x;
    if (i < e) atomicAdd(&g_deg[dst[i]], 1);
}
__global__ void k_scan1(int n) {
    __shared__ int sh[1024];
    int t = threadIdx.x;
    int i = blockIdx.x * 1024 + t;
    int v = (i < n) ? g_deg[i] : 0;
    sh[t] = v;
    __syncthreads();
    for (int off = 1; off < 1024; off <<= 1) {
        int x = (t >= off) ? sh[t - off] : 0;
        __syncthreads();
        sh[t] += x;
        __syncthreads();
    }
    if (i < n) g_scan[i] = sh[t];
    if (t == 1023) g_bsum[blockIdx.x] = sh[1023];
}
__global__ void k_scan23(int n, int nb) {
    __shared__ int bs[128];
    int t = threadIdx.x;
    if (t < nb) bs[t] = g_bsum[t];
    __syncthreads();
    int i = blockIdx.x * blockDim.x + t;
    if (i >= n) return;
    int b = i >> 10;
    int off = 0;
    for (int j = 0; j < b; j++) off += bs[j];
    int v = g_scan[i] + off;
    g_rowptr[i + 1] = v;
    g_rp2[i + 1] = v;
    if (i == 0) { g_rowptr[0] = 0; g_rp2[0] = 0; }
}
__global__ void k_scatter(const int* __restrict__ src,
                          const int* __restrict__ dst,
                          const int* __restrict__ rel, int e) {
    int i = blockIdx.x * blockDim.x + threadIdx.x;
    if (i >= e) return;
    int d = dst[i];
    int pos = atomicAdd(&g_rp2[d], 1);
    g_csr[pos] = src[i] | (rel[i] << 20);
}
// restore zero-invariants for next call (deg, pool, pcnt)
__global__ void k_zero_tail(int n) {
    int i = blockIdx.x * blockDim.x + threadIdx.x;
    if (i < n) g_deg[i] = 0;
    if (i < GNUM * HID) g_pool[i] = 0.f;
    if (i < GNUM) g_pcnt[i] = 0;
}

// ---------------- layer-0 fused dual GEMM with in-place feature build ----------------
__global__ void __launch_bounds__(256, 2)
k_gemm_l0(const int* __restrict__ tok, const float* __restrict__ bbox,
          const float* __restrict__ temb,
          const float* __restrict__ bW, const float* __restrict__ bb,
          const float* __restrict__ Wl, const float* __restrict__ bl,
          const float* __restrict__ Wr, const float* __restrict__ br,
          float* __restrict__ Yl, float* __restrict__ Yr, int n) {
    const int IND = 288, KT = 32;
    __shared__ uint32_t Xs[KT][72];
    __shared__ uint32_t Wsm[KT][264];
    int t = threadIdx.x, lane = t & 31, wid = t >> 5;
    int grp = lane >> 2, thc = lane & 3;
    int mw = wid & 1, nw = wid >> 1;
    int rowbase = blockIdx.x * 64;

    float d[2][8][4];
#pragma unroll
    for (int mi = 0; mi < 2; mi++)
#pragma unroll
        for (int nj = 0; nj < 8; nj++)
#pragma unroll
            for (int q = 0; q < 4; q++) d[mi][nj][q] = 0.f;

    int srow = t >> 2;
    int sks = (t & 3) * 8;
    int grow = rowbase + srow;
    bool rok = grow < n;
    const float* trow = &temb[(size_t)(rok ? tok[grow] : 0) * 256];
    float4 bx = make_float4(0.f, 0.f, 0.f, 0.f);
    if (rok) bx = *(const float4*)&bbox[grow * 4];

    for (int kt = 0; kt < IND; kt += KT) {
        if (kt < 256) {
#pragma unroll
            for (int q = 0; q < 2; q++) {
                float4 v = make_float4(0.f, 0.f, 0.f, 0.f);
                if (rok) v = *(const float4*)&trow[kt + sks + q * 4];
                Xs[sks + q * 4 + 0][srow] = f2tf32(v.x);
                Xs[sks + q * 4 + 1][srow] = f2tf32(v.y);
                Xs[sks + q * 4 + 2][srow] = f2tf32(v.z);
                Xs[sks + q * 4 + 3][srow] = f2tf32(v.w);
            }
        } else {
#pragma unroll
            for (int q = 0; q < 8; q++) {
                int j = sks + q;
                float v = 0.f;
                if (rok)
                    v = bb[j] + bx.x * bW[j] + bx.y * bW[32 + j] +
                        bx.z * bW[64 + j] + bx.w * bW[96 + j];
                Xs[j][srow] = f2tf32(v);
            }
        }
#pragma unroll
        for (int j = 0; j < 8; j++) {
            int id = j * 256 + t;
            int krow = id >> 6, c4 = (id & 63) * 4;
            float4 wv;
            if (c4 < 128) wv = *(const float4*)&Wl[(size_t)(kt + krow) * 128 + c4];
            else          wv = *(const float4*)&Wr[(size_t)(kt + krow) * 128 + (c4 - 128)];
            uint4 u;
            u.x = f2tf32(wv.x); u.y = f2tf32(wv.y);
            u.z = f2tf32(wv.z); u.w = f2tf32(wv.w);
            *(uint4*)&Wsm[krow][c4] = u;
        }
        __syncthreads();
#pragma unroll
        for (int kk = 0; kk < KT; kk += 8) {
            uint32_t a[2][4];
#pragma unroll
            for (int mi = 0; mi < 2; mi++) {
                int r = mw * 32 + mi * 16 + grp;
                a[mi][0] = Xs[kk + thc][r];
                a[mi][1] = Xs[kk + thc][r + 8];
                a[mi][2] = Xs[kk + thc + 4][r];
                a[mi][3] = Xs[kk + thc + 4][r + 8];
            }
            uint32_t b[8][2];
#pragma unroll
            for (int nj = 0; nj < 8; nj++) {
                int c = nw * 64 + nj * 8 + grp;
                b[nj][0] = Wsm[kk + thc][c];
                b[nj][1] = Wsm[kk + thc + 4][c];
            }
#pragma unroll
            for (int mi = 0; mi < 2; mi++)
#pragma unroll
                for (int nj = 0; nj < 8; nj++)
                    mma_tf32(d[mi][nj], a[mi], b[nj]);
        }
        __syncthreads();
    }
#pragma unroll
    for (int mi = 0; mi < 2; mi++) {
        int r0 = rowbase + mw * 32 + mi * 16 + grp;
#pragma unroll
        for (int nj = 0; nj < 8; nj++) {
            int colg = nw * 64 + nj * 8 + 2 * thc;
            const float* B = (colg < 128) ? bl : br;
            float* Y = (colg < 128) ? Yl : Yr;
            int col = colg & 127;
            float2 bv = *(const float2*)&B[col];
            if (r0 < n)
                *(float2*)&Y[(size_t)r0 * 128 + col] =
                    make_float2(d[mi][nj][0] + bv.x, d[mi][nj][1] + bv.y);
            if (r0 + 8 < n)
                *(float2*)&Y[(size_t)(r0 + 8) * 128 + col] =
                    make_float2(d[mi][nj][2] + bv.x, d[mi][nj][3] + bv.y);
        }
    }
}

// ---------------- layers 1-2 GEMM with fused BN-apply in X staging ----------------
__global__ void __launch_bounds__(256, 2)
k_gemm_tc2f(const float* __restrict__ Wl, const float* __restrict__ bl,
            const float* __restrict__ Wr, const float* __restrict__ br,
            float* __restrict__ Yl, float* __restrict__ Yr, int n, int res) {
    const int IND = 128, KT = 32;
    __shared__ uint32_t Xs[KT][72];
    __shared__ uint32_t Wsm[KT][264];
    int t = threadIdx.x, lane = t & 31, wid = t >> 5;
    int grp = lane >> 2, thc = lane & 3;
    int mw = wid & 1, nw = wid >> 1;
    int rowbase = blockIdx.x * 64;

    float d[2][8][4];
#pragma unroll
    for (int mi = 0; mi < 2; mi++)
#pragma unroll
        for (int nj = 0; nj < 8; nj++)
#pragma unroll
            for (int q = 0; q < 4; q++) d[mi][nj][q] = 0.f;

    int srow = t >> 2;
    int sks = (t & 3) * 8;
    int grow = rowbase + srow;
    bool rok = grow < n;
    size_t rowoff = (size_t)(rok ? grow : 0) * 128;

    for (int kt = 0; kt < IND; kt += KT) {
#pragma unroll
        for (int q = 0; q < 2; q++) {
            int kb = kt + sks + q * 4;
            float4 x = make_float4(0.f, 0.f, 0.f, 0.f);
            if (rok) {
                float4 v = *(const float4*)&g_agg[rowoff + kb];
                float4 s4 = *(const float4*)&g_scale[kb];
                float4 f4 = *(const float4*)&g_shift[kb];
                x.x = s4.x * v.x + f4.x;
                x.y = s4.y * v.y + f4.y;
                x.z = s4.z * v.z + f4.z;
                x.w = s4.w * v.w + f4.w;
                if (res) {
                    float4 hp = *(const float4*)&g_h[rowoff + kb];
                    x.x += hp.x; x.y += hp.y; x.z += hp.z; x.w += hp.w;
                }
                *(float4*)&g_h[rowoff + kb] = x;
            }
            Xs[sks + q * 4 + 0][srow] = f2tf32(x.x);
            Xs[sks + q * 4 + 1][srow] = f2tf32(x.y);
            Xs[sks + q * 4 + 2][srow] = f2tf32(x.z);
            Xs[sks + q * 4 + 3][srow] = f2tf32(x.w);
        }
#pragma unroll
        for (int j = 0; j < 8; j++) {
            int id = j * 256 + t;
            int krow = id >> 6, c4 = (id & 63) * 4;
            float4 wv;
            if (c4 < 128) wv = *(const float4*)&Wl[(size_t)(kt + krow) * 128 + c4];
            else          wv = *(const float4*)&Wr[(size_t)(kt + krow) * 128 + (c4 - 128)];
            uint4 u;
            u.x = f2tf32(wv.x); u.y = f2tf32(wv.y);
            u.z = f2tf32(wv.z); u.w = f2tf32(wv.w);
            *(uint4*)&Wsm[krow][c4] = u;
        }
        __syncthreads();
#pragma unroll
        for (int kk = 0; kk < KT; kk += 8) {
            uint32_t a[2][4];
#pragma unroll
            for (int mi = 0; mi < 2; mi++) {
                int r = mw * 32 + mi * 16 + grp;
                a[mi][0] = Xs[kk + thc][r];
                a[mi][1] = Xs[kk + thc][r + 8];
                a[mi][2] = Xs[kk + thc + 4][r];
                a[mi][3] = Xs[kk + thc + 4][r + 8];
            }
            uint32_t b[8][2];
#pragma unroll
            for (int nj = 0; nj < 8; nj++) {
                int c = nw * 64 + nj * 8 + grp;
                b[nj][0] = Wsm[kk + thc][c];
                b[nj][1] = Wsm[kk + thc + 4][c];
            }
#pragma unroll
            for (int mi = 0; mi < 2; mi++)
#pragma unroll
                for (int nj = 0; nj < 8; nj++)
                    mma_tf32(d[mi][nj], a[mi], b[nj]);
        }
        __syncthreads();
    }
#pragma unroll
    for (int mi = 0; mi < 2; mi++) {
        int r0 = rowbase + mw * 32 + mi * 16 + grp;
#pragma unroll
        for (int nj = 0; nj < 8; nj++) {
            int colg = nw * 64 + nj * 8 + 2 * thc;
            const float* B = (colg < 128) ? bl : br;
            float* Y = (colg < 128) ? Yl : Yr;
            int col = colg & 127;
            float2 bv = *(const float2*)&B[col];
            if (r0 < n)
                *(float2*)&Y[(size_t)r0 * 128 + col] =
                    make_float2(d[mi][nj][0] + bv.x, d[mi][nj][1] + bv.y);
            if (r0 + 8 < n)
                *(float2*)&Y[(size_t)(r0 + 8) * 128 + col] =
                    make_float2(d[mi][nj][2] + bv.x, d[mi][nj][3] + bv.y);
        }
    }
}

// ---------------- fused edge pass (unroll-2, fp32, fmax-leaky, atomic BN sums) ----------------
__device__ __forceinline__ float lrelu(float m) { return fmaxf(m, NEG * m); }

__global__ void __launch_bounds__(256) k_edge(const float* __restrict__ att,
                                              const float* __restrict__ bias,
                                              const float* __restrict__ relemb,
                                              const float* __restrict__ We, int n) {
    __shared__ float ee[RELN * HID];
    __shared__ float red[8][32][8];
    int t = threadIdx.x;
    for (int i = t; i < RELN * HID; i += 256) {
        int r = i >> 7, j = i & 127;
        float s = 0.f;
#pragma unroll
        for (int c = 0; c < 16; c++) s += relemb[r * 16 + c] * We[c * 128 + j];
        ee[i] = s;
    }
    __syncthreads();
    int lane = t & 31, wid = t >> 5;
    float4 av = *(const float4*)&att[(lane >> 2) * 16 + (lane & 3) * 4];
    float4 bv = *(const float4*)&bias[lane * 4];
    float ps0 = 0.f, ps1 = 0.f, ps2 = 0.f, ps3 = 0.f;
    float pq0 = 0.f, pq1 = 0.f, pq2 = 0.f, pq3 = 0.f;

    for (int node = blockIdx.x * 8 + wid; node < n; node += EG * 8) {
        int r0 = g_rowptr[node], r1 = g_rowptr[node + 1];
        float4 xr = *(const float4*)&g_xr[(size_t)node * 128 + lane * 4];
        float4 acc = {0.f, 0.f, 0.f, 0.f};
        float den = 0.f;
        int i = r0;
        for (; i + 2 <= r1; i += 2) {
            int pe0 = g_csr[i], pe1 = g_csr[i + 1];
            float4 xl0 = *(const float4*)&g_xl[(size_t)(pe0 & 0xFFFFF) * 128 + lane * 4];
            float4 ev0 = *(const float4*)&ee[(pe0 >> 20) * 128 + lane * 4];
            float4 xl1 = *(const float4*)&g_xl[(size_t)(pe1 & 0xFFFFF) * 128 + lane * 4];
            float4 ev1 = *(const float4*)&ee[(pe1 >> 20) * 128 + lane * 4];
            float s0, s1;
            s0  = lrelu(xl0.x + xr.x + ev0.x) * av.x;
            s0 += lrelu(xl0.y + xr.y + ev0.y) * av.y;
            s0 += lrelu(xl0.z + xr.z + ev0.z) * av.z;
            s0 += lrelu(xl0.w + xr.w + ev0.w) * av.w;
            s1  = lrelu(xl1.x + xr.x + ev1.x) * av.x;
            s1 += lrelu(xl1.y + xr.y + ev1.y) * av.y;
            s1 += lrelu(xl1.z + xr.z + ev1.z) * av.z;
            s1 += lrelu(xl1.w + xr.w + ev1.w) * av.w;
            s0 += __shfl_xor_sync(0xffffffffu, s0, 1);
            s0 += __shfl_xor_sync(0xffffffffu, s0, 2);
            s1 += __shfl_xor_sync(0xffffffffu, s1, 1);
            s1 += __shfl_xor_sync(0xffffffffu, s1, 2);
            float p0 = __expf(s0), p1 = __expf(s1);
            den += p0 + p1;
            acc.x += p0 * xl0.x + p1 * xl1.x;
            acc.y += p0 * xl0.y + p1 * xl1.y;
            acc.z += p0 * xl0.z + p1 * xl1.z;
            acc.w += p0 * xl0.w + p1 * xl1.w;
        }
        if (i < r1) {
            int pe0 = g_csr[i];
            float4 xl0 = *(const float4*)&g_xl[(size_t)(pe0 & 0xFFFFF) * 128 + lane * 4];
            float4 ev0 = *(const float4*)&ee[(pe0 >> 20) * 128 + lane * 4];
            float s0;
            s0  = lrelu(xl0.x + xr.x + ev0.x) * av.x;
            s0 += lrelu(xl0.y + xr.y + ev0.y) * av.y;
            s0 += lrelu(xl0.z + xr.z + ev0.z) * av.z;
            s0 += lrelu(xl0.w + xr.w + ev0.w) * av.w;
            s0 += __shfl_xor_sync(0xffffffffu, s0, 1);
            s0 += __shfl_xor_sync(0xffffffffu, s0, 2);
            float p0 = __expf(s0);
            den += p0;
            acc.x += p0 * xl0.x;
            acc.y += p0 * xl0.y;
            acc.z += p0 * xl0.z;
            acc.w += p0 * xl0.w;
        }
        float inv = __frcp_rn(fmaxf(den, 1e-16f));
        float4 o;
        o.x = fmaxf(acc.x * inv + bv.x, 0.f);
        o.y = fmaxf(acc.y * inv + bv.y, 0.f);
        o.z = fmaxf(acc.z * inv + bv.z, 0.f);
        o.w = fmaxf(acc.w * inv + bv.w, 0.f);
        *(float4*)&g_agg[(size_t)node * 128 + lane * 4] = o;
        ps0 += o.x; ps1 += o.y; ps2 += o.z; ps3 += o.w;
        pq0 += o.x * o.x; pq1 += o.y * o.y; pq2 += o.z * o.z; pq3 += o.w * o.w;
    }
    red[wid][lane][0] = ps0; red[wid][lane][1] = ps1;
    red[wid][lane][2] = ps2; red[wid][lane][3] = ps3;
    red[wid][lane][4] = pq0; red[wid][lane][5] = pq1;
    red[wid][lane][6] = pq2; red[wid][lane][7] = pq3;
    __syncthreads();
    int stat = t >> 7, ch = t & 127;
    int ln = ch >> 2, j = ch & 3;
    float s = 0.f;
#pragma unroll
    for (int w = 0; w < 8; w++) s += red[w][ln][stat * 4 + j];
    atomicAdd(&g_sum[t], s);   // [0..127]=sum, [128..255]=sumsq
}

// ---------------- BN finalize (trivial; self-zeroing for next layer) ----------------
__global__ void k_bnr2(const float* __restrict__ gamma,
                       const float* __restrict__ beta, int n) {
    int t = threadIdx.x;   // 128 threads
    float s = g_sum[t];
    float q = g_sum[t + 128];
    g_sum[t] = 0.f;
    g_sum[t + 128] = 0.f;
    float inv_n = 1.0f / (float)n;
    float mu = s * inv_n;
    float var = q * inv_n - mu * mu;
    float rs = rsqrtf(var + 1e-5f);
    float sc = gamma[t] * rs;
    g_scale[t] = sc;
    g_shift[t] = beta[t] - mu * sc;
}

// ---------------- pooling (fused with final BN apply + residual) ----------------
__global__ void k_pool_apply(const int* __restrict__ batch, int n) {
    const int CHUNK = 256;
    int t = threadIdx.x;
    float sc = g_scale[t], sf = g_shift[t];
    int r0 = blockIdx.x * CHUNK;
    int rend = min(r0 + CHUNK, n);
    float a = 0.f;
    int lc = 0, cur = -1;
    for (int r = r0; r < rend; r++) {
        int g = batch[r];
        if (g != cur) {
            if (cur >= 0) {
                atomicAdd(&g_pool[cur * 128 + t], a);
                if (t == 0) atomicAdd(&g_pcnt[cur], lc);
            }
            a = 0.f;
            lc = 0;
            cur = g;
        }
        a += g_h[(size_t)r * 128 + t] + sc * g_agg[(size_t)r * 128 + t] + sf;
        lc++;
    }
    if (cur >= 0) {
        atomicAdd(&g_pool[cur * 128 + t], a);
        if (t == 0) atomicAdd(&g_pcnt[cur], lc);
    }
}
__global__ void k_pool_fin(float* __restrict__ out) {
    int i = blockIdx.x * blockDim.x + threadIdx.x;
    if (i >= GNUM * HID) return;
    out[i] = g_pool[i] / fmaxf((float)g_pcnt[i >> 7], 1.0f);
}

// ---------------- host launch ----------------
extern "C" void kernel_launch(void* const* d_in, const int* in_sizes, int n_in,
                              void* d_out, int out_size) {
    const int* tok = (const int*)d_in[0];
    const float* bbox = (const float*)d_in[1];
    const int* ei = (const int*)d_in[2];
    const int* eattr = (const int*)d_in[3];
    const int* batch = (const int*)d_in[4];
    const float* temb = (const float*)d_in[5];
    const float* bW = (const float*)d_in[6];
    const float* bb = (const float*)d_in[7];
    const float* relemb = (const float*)d_in[8];
    const float* Wl0 = (const float*)d_in[9];
    const float* bl0 = (const float*)d_in[10];
    const float* Wr0 = (const float*)d_in[11];
    const float* br0 = (const float*)d_in[12];
    const float* We0 = (const float*)d_in[13];
    const float* att0 = (const float*)d_in[14];
    const float* bias0 = (const float*)d_in[15];
    const float* gamma0 = (const float*)d_in[16];
    const float* beta0 = (const float*)d_in[17];
    const float* WlS = (const float*)d_in[18];
    const float* blS = (const float*)d_in[19];
    const float* WrS = (const float*)d_in[20];
    const float* brS = (const float*)d_in[21];
    const float* WeS = (const float*)d_in[22];
    const float* attS = (const float*)d_in[23];
    const float* biasS = (const float*)d_in[24];
    const float* gammaS = (const float*)d_in[25];
    const float* betaS = (const float*)d_in[26];

    int n = in_sizes[0];
    int e = in_sizes[3];
    const int* src = ei;
    const int* dst = ei + e;

    float *p_xl, *p_xr;
    cudaGetSymbolAddress((void**)&p_xl, g_xl);
    cudaGetSymbolAddress((void**)&p_xr, g_xr);

    int gN = (n + 255) / 256;
    int gE = (e + 255) / 256;
    int nbScan = (n + 1023) / 1024;
    int gemmGrid = (n + 63) / 64;

    k_hist<<<gE, 256>>>(dst, e);
    k_scan1<<<nbScan, 1024>>>(n);
    k_scan23<<<gN, 256>>>(n, nbScan);
    // idx 3: layer-0 GEMM (CSR-independent) -> ncu sample window lands here
    k_gemm_l0<<<gemmGrid, 256>>>(tok, bbox, temb, bW, bb,
                                 Wl0, bl0, Wr0, br0, p_xl, p_xr, n);
    k_scatter<<<gE, 256>>>(src, dst, eattr, e);

    for (int l = 0; l < 3; l++) {
        const float *Wl, *bl, *Wr, *br, *We, *att, *bias, *gamma, *beta;
        if (l == 0) {
            Wl = Wl0; bl = bl0; Wr = Wr0; br = br0; We = We0;
            att = att0; bias = bias0; gamma = gamma0; beta = beta0;
        } else {
            int j = l - 1;
            Wl = WlS + (size_t)j * 128 * 128; bl = blS + j * 128;
            Wr = WrS + (size_t)j * 128 * 128; br = brS + j * 128;
            We = WeS + (size_t)j * 16 * 128;
            att = attS + j * 128;
            bias = biasS + j * 128; gamma = gammaS + j * 128; beta = betaS + j * 128;
        }
        if (l > 0) {
            k_gemm_tc2f<<<gemmGrid, 256>>>(Wl, bl, Wr, br, p_xl, p_xr, n, l - 1);
        }
        k_edge<<<EG, 256>>>(att, bias, relemb, We, n);
        k_bnr2<<<1, 128>>>(gamma, beta, n);
    }

    k_pool_apply<<<(n + 255) / 256, 128>>>(batch, n);
    k_pool_fin<<<(GNUM * HID + 255) / 256, 256>>>((float*)d_out);
    k_zero_tail<<<gN, 256>>>(n);
}

// round 14
// speedup vs baseline: 1.1442x; 1.0600x over previous
#include <cuda_runtime.h>
#include <cstdint>

#define NMAX 100000
#define EMAX 1600000
#define HID 128
#define GNUM 64
#define RELN 51
#define NEG 0.2f
#define EG 740   // edge-pass grid (5 * 148)

// ---------------- scratch ----------------
__device__ float g_h[(size_t)NMAX * HID];
__device__ float g_xl[(size_t)NMAX * HID];
__device__ float g_xr[(size_t)NMAX * HID];
__device__ float g_agg[(size_t)NMAX * HID];
__device__ float g_sum[256];          // BN sums/sumsqs; zero at edge launch (zero-init + bnr2 self-zero)
__device__ float g_scale[HID];
__device__ float g_shift[HID];
__device__ float g_pool[GNUM * HID];  // zero at pool launch (zero-init + tail zero)
__device__ int   g_pcnt[GNUM];
__device__ int   g_deg[NMAX];         // zero at entry (zero-init + tail zero)
__device__ int   g_rowptr[NMAX + 1];
__device__ int   g_rp2[NMAX + 1];
__device__ int   g_scan[NMAX];
__device__ int   g_bsum[128];
__device__ int   g_csr[EMAX];

// ---------------- tf32 helpers ----------------
__device__ __forceinline__ uint32_t f2tf32(float x) {
    uint32_t r;
    asm("cvt.rna.tf32.f32 %0, %1;" : "=r"(r) : "f"(x));
    return r;
}
__device__ __forceinline__ void mma_tf32(float d[4], const uint32_t a[4],
                                         const uint32_t b[2]) {
    asm volatile(
        "mma.sync.aligned.m16n8k8.row.col.f32.tf32.tf32.f32 "
        "{%0,%1,%2,%3}, {%4,%5,%6,%7}, {%8,%9}, {%0,%1,%2,%3};"
        : "+f"(d[0]), "+f"(d[1]), "+f"(d[2]), "+f"(d[3])
        : "r"(a[0]), "r"(a[1]), "r"(a[2]), "r"(a[3]), "r"(b[0]), "r"(b[1]));
}

// ---------------- CSR build ----------------
__global__ void k_hist(const int* __restrict__ dst, int e) {
    int i = blockIdx.x * blockDim.x + threadIdx.x;
    if (i < e) atomicAdd(&g_deg[dst[i]], 1);
}
__global__ void k_scan1(int n) {
    __shared__ int sh[1024];
    int t = threadIdx.x;
    int i = blockIdx.x * 1024 + t;
    int v = (i < n) ? g_deg[i] : 0;
    sh[t] = v;
    __syncthreads();
    for (int off = 1; off < 1024; off <<= 1) {
        int x = (t >= off) ? sh[t - off] : 0;
        __syncthreads();
        sh[t] += x;
        __syncthreads();
    }
    if (i < n) g_scan[i] = sh[t];
    if (t == 1023) g_bsum[blockIdx.x] = sh[1023];
}
__global__ void k_scan23(int n, int nb) {
    __shared__ int bs[128];
    int t = threadIdx.x;
    if (t < nb) bs[t] = g_bsum[t];
    __syncthreads();
    int i = blockIdx.x * blockDim.x + t;
    if (i >= n) return;
    int b = i >> 10;
    int off = 0;
    for (int j = 0; j < b; j++) off += bs[j];
    int v = g_scan[i] + off;
    g_rowptr[i + 1] = v;
    g_rp2[i + 1] = v;
    if (i == 0) { g_rowptr[0] = 0; g_rp2[0] = 0; }
}
__global__ void k_scatter(const int* __restrict__ src,
                          const int* __restrict__ dst,
                          const int* __restrict__ rel, int e) {
    int i = blockIdx.x * blockDim.x + threadIdx.x;
    if (i >= e) return;
    int d = dst[i];
    int pos = atomicAdd(&g_rp2[d], 1);
    g_csr[pos] = src[i] | (rel[i] << 20);
}
__global__ void k_zero_tail(int n) {
    int i = blockIdx.x * blockDim.x + threadIdx.x;
    if (i < n) g_deg[i] = 0;
    if (i < GNUM * HID) g_pool[i] = 0.f;
    if (i < GNUM) g_pcnt[i] = 0;
}

// ---------------- layer-0 fused dual GEMM with in-place feature build ----------------
__global__ void __launch_bounds__(256, 2)
k_gemm_l0(const int* __restrict__ tok, const float* __restrict__ bbox,
          const float* __restrict__ temb,
          const float* __restrict__ bW, const float* __restrict__ bb,
          const float* __restrict__ Wl, const float* __restrict__ bl,
          const float* __restrict__ Wr, const float* __restrict__ br,
          float* __restrict__ Yl, float* __restrict__ Yr, int n) {
    const int IND = 288, KT = 32;
    __shared__ uint32_t Xs[KT][72];
    __shared__ uint32_t Wsm[KT][264];
    int t = threadIdx.x, lane = t & 31, wid = t >> 5;
    int grp = lane >> 2, thc = lane & 3;
    int mw = wid & 1, nw = wid >> 1;
    int rowbase = blockIdx.x * 64;

    float d[2][8][4];
#pragma unroll
    for (int mi = 0; mi < 2; mi++)
#pragma unroll
        for (int nj = 0; nj < 8; nj++)
#pragma unroll
            for (int q = 0; q < 4; q++) d[mi][nj][q] = 0.f;

    int srow = t >> 2;
    int sks = (t & 3) * 8;
    int grow = rowbase + srow;
    bool rok = grow < n;
    const float* trow = &temb[(size_t)(rok ? tok[grow] : 0) * 256];
    float4 bx = make_float4(0.f, 0.f, 0.f, 0.f);
    if (rok) bx = *(const float4*)&bbox[grow * 4];

    for (int kt = 0; kt < IND; kt += KT) {
        if (kt < 256) {
#pragma unroll
            for (int q = 0; q < 2; q++) {
                float4 v = make_float4(0.f, 0.f, 0.f, 0.f);
                if (rok) v = *(const float4*)&trow[kt + sks + q * 4];
                Xs[sks + q * 4 + 0][srow] = f2tf32(v.x);
                Xs[sks + q * 4 + 1][srow] = f2tf32(v.y);
                Xs[sks + q * 4 + 2][srow] = f2tf32(v.z);
                Xs[sks + q * 4 + 3][srow] = f2tf32(v.w);
            }
        } else {
#pragma unroll
            for (int q = 0; q < 8; q++) {
                int j = sks + q;
                float v = 0.f;
                if (rok)
                    v = bb[j] + bx.x * bW[j] + bx.y * bW[32 + j] +
                        bx.z * bW[64 + j] + bx.w * bW[96 + j];
                Xs[j][srow] = f2tf32(v);
            }
        }
#pragma unroll
        for (int j = 0; j < 8; j++) {
            int id = j * 256 + t;
            int krow = id >> 6, c4 = (id & 63) * 4;
            float4 wv;
            if (c4 < 128) wv = *(const float4*)&Wl[(size_t)(kt + krow) * 128 + c4];
            else          wv = *(const float4*)&Wr[(size_t)(kt + krow) * 128 + (c4 - 128)];
            uint4 u;
            u.x = f2tf32(wv.x); u.y = f2tf32(wv.y);
            u.z = f2tf32(wv.z); u.w = f2tf32(wv.w);
            *(uint4*)&Wsm[krow][c4] = u;
        }
        __syncthreads();
#pragma unroll
        for (int kk = 0; kk < KT; kk += 8) {
            uint32_t a[2][4];
#pragma unroll
            for (int mi = 0; mi < 2; mi++) {
                int r = mw * 32 + mi * 16 + grp;
                a[mi][0] = Xs[kk + thc][r];
                a[mi][1] = Xs[kk + thc][r + 8];
                a[mi][2] = Xs[kk + thc + 4][r];
                a[mi][3] = Xs[kk + thc + 4][r + 8];
            }
            uint32_t b[8][2];
#pragma unroll
            for (int nj = 0; nj < 8; nj++) {
                int c = nw * 64 + nj * 8 + grp;
                b[nj][0] = Wsm[kk + thc][c];
                b[nj][1] = Wsm[kk + thc + 4][c];
            }
#pragma unroll
            for (int mi = 0; mi < 2; mi++)
#pragma unroll
                for (int nj = 0; nj < 8; nj++)
                    mma_tf32(d[mi][nj], a[mi], b[nj]);
        }
        __syncthreads();
    }
#pragma unroll
    for (int mi = 0; mi < 2; mi++) {
        int r0 = rowbase + mw * 32 + mi * 16 + grp;
#pragma unroll
        for (int nj = 0; nj < 8; nj++) {
            int colg = nw * 64 + nj * 8 + 2 * thc;
            const float* B = (colg < 128) ? bl : br;
            float* Y = (colg < 128) ? Yl : Yr;
            int col = colg & 127;
            float2 bv = *(const float2*)&B[col];
            if (r0 < n)
                *(float2*)&Y[(size_t)r0 * 128 + col] =
                    make_float2(d[mi][nj][0] + bv.x, d[mi][nj][1] + bv.y);
            if (r0 + 8 < n)
                *(float2*)&Y[(size_t)(r0 + 8) * 128 + col] =
                    make_float2(d[mi][nj][2] + bv.x, d[mi][nj][3] + bv.y);
        }
    }
}

// ---------------- layers 1-2 GEMM with fused BN-apply in X staging ----------------
__global__ void __launch_bounds__(256, 2)
k_gemm_tc2f(const float* __restrict__ Wl, const float* __restrict__ bl,
            const float* __restrict__ Wr, const float* __restrict__ br,
            float* __restrict__ Yl, float* __restrict__ Yr, int n, int res) {
    const int IND = 128, KT = 32;
    __shared__ uint32_t Xs[KT][72];
    __shared__ uint32_t Wsm[KT][264];
    int t = threadIdx.x, lane = t & 31, wid = t >> 5;
    int grp = lane >> 2, thc = lane & 3;
    int mw = wid & 1, nw = wid >> 1;
    int rowbase = blockIdx.x * 64;

    float d[2][8][4];
#pragma unroll
    for (int mi = 0; mi < 2; mi++)
#pragma unroll
        for (int nj = 0; nj < 8; nj++)
#pragma unroll
            for (int q = 0; q < 4; q++) d[mi][nj][q] = 0.f;

    int srow = t >> 2;
    int sks = (t & 3) * 8;
    int grow = rowbase + srow;
    bool rok = grow < n;
    size_t rowoff = (size_t)(rok ? grow : 0) * 128;

    for (int kt = 0; kt < IND; kt += KT) {
#pragma unroll
        for (int q = 0; q < 2; q++) {
            int kb = kt + sks + q * 4;
            float4 x = make_float4(0.f, 0.f, 0.f, 0.f);
            if (rok) {
                float4 v = *(const float4*)&g_agg[rowoff + kb];
                float4 s4 = *(const float4*)&g_scale[kb];
                float4 f4 = *(const float4*)&g_shift[kb];
                x.x = s4.x * v.x + f4.x;
                x.y = s4.y * v.y + f4.y;
                x.z = s4.z * v.z + f4.z;
                x.w = s4.w * v.w + f4.w;
                if (res) {
                    float4 hp = *(const float4*)&g_h[rowoff + kb];
                    x.x += hp.x; x.y += hp.y; x.z += hp.z; x.w += hp.w;
                }
                *(float4*)&g_h[rowoff + kb] = x;
            }
            Xs[sks + q * 4 + 0][srow] = f2tf32(x.x);
            Xs[sks + q * 4 + 1][srow] = f2tf32(x.y);
            Xs[sks + q * 4 + 2][srow] = f2tf32(x.z);
            Xs[sks + q * 4 + 3][srow] = f2tf32(x.w);
        }
#pragma unroll
        for (int j = 0; j < 8; j++) {
            int id = j * 256 + t;
            int krow = id >> 6, c4 = (id & 63) * 4;
            float4 wv;
            if (c4 < 128) wv = *(const float4*)&Wl[(size_t)(kt + krow) * 128 + c4];
            else          wv = *(const float4*)&Wr[(size_t)(kt + krow) * 128 + (c4 - 128)];
            uint4 u;
            u.x = f2tf32(wv.x); u.y = f2tf32(wv.y);
            u.z = f2tf32(wv.z); u.w = f2tf32(wv.w);
            *(uint4*)&Wsm[krow][c4] = u;
        }
        __syncthreads();
#pragma unroll
        for (int kk = 0; kk < KT; kk += 8) {
            uint32_t a[2][4];
#pragma unroll
            for (int mi = 0; mi < 2; mi++) {
                int r = mw * 32 + mi * 16 + grp;
                a[mi][0] = Xs[kk + thc][r];
                a[mi][1] = Xs[kk + thc][r + 8];
                a[mi][2] = Xs[kk + thc + 4][r];
                a[mi][3] = Xs[kk + thc + 4][r + 8];
            }
            uint32_t b[8][2];
#pragma unroll
            for (int nj = 0; nj < 8; nj++) {
                int c = nw * 64 + nj * 8 + grp;
                b[nj][0] = Wsm[kk + thc][c];
                b[nj][1] = Wsm[kk + thc + 4][c];
            }
#pragma unroll
            for (int mi = 0; mi < 2; mi++)
#pragma unroll
                for (int nj = 0; nj < 8; nj++)
                    mma_tf32(d[mi][nj], a[mi], b[nj]);
        }
        __syncthreads();
    }
#pragma unroll
    for (int mi = 0; mi < 2; mi++) {
        int r0 = rowbase + mw * 32 + mi * 16 + grp;
#pragma unroll
        for (int nj = 0; nj < 8; nj++) {
            int colg = nw * 64 + nj * 8 + 2 * thc;
            const float* B = (colg < 128) ? bl : br;
            float* Y = (colg < 128) ? Yl : Yr;
            int col = colg & 127;
            float2 bv = *(const float2*)&B[col];
            if (r0 < n)
                *(float2*)&Y[(size_t)r0 * 128 + col] =
                    make_float2(d[mi][nj][0] + bv.x, d[mi][nj][1] + bv.y);
            if (r0 + 8 < n)
                *(float2*)&Y[(size_t)(r0 + 8) * 128 + col] =
                    make_float2(d[mi][nj][2] + bv.x, d[mi][nj][3] + bv.y);
        }
    }
}

// ---------------- fused edge pass (unroll-2, 5 CTAs/SM) ----------------
__device__ __forceinline__ float lrelu(float m) { return fmaxf(m, NEG * m); }

__global__ void __launch_bounds__(256, 5)
k_edge(const float* __restrict__ att, const float* __restrict__ bias,
       const float* __restrict__ relemb, const float* __restrict__ We, int n) {
    __shared__ float ee[RELN * HID];
    __shared__ float red[8][32][8];
    int t = threadIdx.x;
    for (int i = t; i < RELN * HID; i += 256) {
        int r = i >> 7, j = i & 127;
        float s = 0.f;
#pragma unroll
        for (int c = 0; c < 16; c++) s += relemb[r * 16 + c] * We[c * 128 + j];
        ee[i] = s;
    }
    __syncthreads();
    int lane = t & 31, wid = t >> 5;
    float4 av = *(const float4*)&att[(lane >> 2) * 16 + (lane & 3) * 4];
    float4 bv = *(const float4*)&bias[lane * 4];
    float ps0 = 0.f, ps1 = 0.f, ps2 = 0.f, ps3 = 0.f;
    float pq0 = 0.f, pq1 = 0.f, pq2 = 0.f, pq3 = 0.f;

    for (int node = blockIdx.x * 8 + wid; node < n; node += EG * 8) {
        int r0 = g_rowptr[node], r1 = g_rowptr[node + 1];
        float4 xr = *(const float4*)&g_xr[(size_t)node * 128 + lane * 4];
        float4 acc = {0.f, 0.f, 0.f, 0.f};
        float den = 0.f;
        int i = r0;
        for (; i + 2 <= r1; i += 2) {
            int pe0 = g_csr[i], pe1 = g_csr[i + 1];
            float4 xl0 = *(const float4*)&g_xl[(size_t)(pe0 & 0xFFFFF) * 128 + lane * 4];
            float4 ev0 = *(const float4*)&ee[(pe0 >> 20) * 128 + lane * 4];
            float4 xl1 = *(const float4*)&g_xl[(size_t)(pe1 & 0xFFFFF) * 128 + lane * 4];
            float4 ev1 = *(const float4*)&ee[(pe1 >> 20) * 128 + lane * 4];
            float s0, s1;
            s0  = lrelu(xl0.x + xr.x + ev0.x) * av.x;
            s0 += lrelu(xl0.y + xr.y + ev0.y) * av.y;
            s0 += lrelu(xl0.z + xr.z + ev0.z) * av.z;
            s0 += lrelu(xl0.w + xr.w + ev0.w) * av.w;
            s1  = lrelu(xl1.x + xr.x + ev1.x) * av.x;
            s1 += lrelu(xl1.y + xr.y + ev1.y) * av.y;
            s1 += lrelu(xl1.z + xr.z + ev1.z) * av.z;
            s1 += lrelu(xl1.w + xr.w + ev1.w) * av.w;
            s0 += __shfl_xor_sync(0xffffffffu, s0, 1);
            s0 += __shfl_xor_sync(0xffffffffu, s0, 2);
            s1 += __shfl_xor_sync(0xffffffffu, s1, 1);
            s1 += __shfl_xor_sync(0xffffffffu, s1, 2);
            float p0 = __expf(s0), p1 = __expf(s1);
            den += p0 + p1;
            acc.x += p0 * xl0.x + p1 * xl1.x;
            acc.y += p0 * xl0.y + p1 * xl1.y;
            acc.z += p0 * xl0.z + p1 * xl1.z;
            acc.w += p0 * xl0.w + p1 * xl1.w;
        }
        if (i < r1) {
            int pe0 = g_csr[i];
            float4 xl0 = *(const float4*)&g_xl[(size_t)(pe0 & 0xFFFFF) * 128 + lane * 4];
            float4 ev0 = *(const float4*)&ee[(pe0 >> 20) * 128 + lane * 4];
            float s0;
            s0  = lrelu(xl0.x + xr.x + ev0.x) * av.x;
            s0 += lrelu(xl0.y + xr.y + ev0.y) * av.y;
            s0 += lrelu(xl0.z + xr.z + ev0.z) * av.z;
            s0 += lrelu(xl0.w + xr.w + ev0.w) * av.w;
            s0 += __shfl_xor_sync(0xffffffffu, s0, 1);
            s0 += __shfl_xor_sync(0xffffffffu, s0, 2);
            float p0 = __expf(s0);
            den += p0;
            acc.x += p0 * xl0.x;
            acc.y += p0 * xl0.y;
            acc.z += p0 * xl0.z;
            acc.w += p0 * xl0.w;
        }
        float inv = __frcp_rn(fmaxf(den, 1e-16f));
        float4 o;
        o.x = fmaxf(acc.x * inv + bv.x, 0.f);
        o.y = fmaxf(acc.y * inv + bv.y, 0.f);
        o.z = fmaxf(acc.z * inv + bv.z, 0.f);
        o.w = fmaxf(acc.w * inv + bv.w, 0.f);
        *(float4*)&g_agg[(size_t)node * 128 + lane * 4] = o;
        ps0 += o.x; ps1 += o.y; ps2 += o.z; ps3 += o.w;
        pq0 += o.x * o.x; pq1 += o.y * o.y; pq2 += o.z * o.z; pq3 += o.w * o.w;
    }
    red[wid][lane][0] = ps0; red[wid][lane][1] = ps1;
    red[wid][lane][2] = ps2; red[wid][lane][3] = ps3;
    red[wid][lane][4] = pq0; red[wid][lane][5] = pq1;
    red[wid][lane][6] = pq2; red[wid][lane][7] = pq3;
    __syncthreads();
    int stat = t >> 7, ch = t & 127;
    int ln = ch >> 2, j = ch & 3;
    float s = 0.f;
#pragma unroll
    for (int w = 0; w < 8; w++) s += red[w][ln][stat * 4 + j];
    atomicAdd(&g_sum[t], s);
}

// ---------------- BN finalize (trivial; self-zeroing) ----------------
__global__ void k_bnr2(const float* __restrict__ gamma,
                       const float* __restrict__ beta, int n) {
    int t = threadIdx.x;
    float s = g_sum[t];
    float q = g_sum[t + 128];
    g_sum[t] = 0.f;
    g_sum[t + 128] = 0.f;
    float inv_n = 1.0f / (float)n;
    float mu = s * inv_n;
    float var = q * inv_n - mu * mu;
    float rs = rsqrtf(var + 1e-5f);
    float sc = gamma[t] * rs;
    g_scale[t] = sc;
    g_shift[t] = beta[t] - mu * sc;
}

// ---------------- pooling (fused with final BN apply + residual) ----------------
__global__ void k_pool_apply(const int* __restrict__ batch, int n) {
    const int CHUNK = 256;
    int t = threadIdx.x;
    float sc = g_scale[t], sf = g_shift[t];
    int r0 = blockIdx.x * CHUNK;
    int rend = min(r0 + CHUNK, n);
    float a = 0.f;
    int lc = 0, cur = -1;
    for (int r = r0; r < rend; r++) {
        int g = batch[r];
        if (g != cur) {
            if (cur >= 0) {
                atomicAdd(&g_pool[cur * 128 + t], a);
                if (t == 0) atomicAdd(&g_pcnt[cur], lc);
            }
            a = 0.f;
            lc = 0;
            cur = g;
        }
        a += g_h[(size_t)r * 128 + t] + sc * g_agg[(size_t)r * 128 + t] + sf;
        lc++;
    }
    if (cur >= 0) {
        atomicAdd(&g_pool[cur * 128 + t], a);
        if (t == 0) atomicAdd(&g_pcnt[cur], lc);
    }
}
__global__ void k_pool_fin(float* __restrict__ out) {
    int i = blockIdx.x * blockDim.x + threadIdx.x;
    if (i >= GNUM * HID) return;
    out[i] = g_pool[i] / fmaxf((float)g_pcnt[i >> 7], 1.0f);
}

// ---------------- host launch ----------------
extern "C" void kernel_launch(void* const* d_in, const int* in_sizes, int n_in,
                              void* d_out, int out_size) {
    const int* tok = (const int*)d_in[0];
    const float* bbox = (const float*)d_in[1];
    const int* ei = (const int*)d_in[2];
    const int* eattr = (const int*)d_in[3];
    const int* batch = (const int*)d_in[4];
    const float* temb = (const float*)d_in[5];
    const float* bW = (const float*)d_in[6];
    const float* bb = (const float*)d_in[7];
    const float* relemb = (const float*)d_in[8];
    const float* Wl0 = (const float*)d_in[9];
    const float* bl0 = (const float*)d_in[10];
    const float* Wr0 = (const float*)d_in[11];
    const float* br0 = (const float*)d_in[12];
    const float* We0 = (const float*)d_in[13];
    const float* att0 = (const float*)d_in[14];
    const float* bias0 = (const float*)d_in[15];
    const float* gamma0 = (const float*)d_in[16];
    const float* beta0 = (const float*)d_in[17];
    const float* WlS = (const float*)d_in[18];
    const float* blS = (const float*)d_in[19];
    const float* WrS = (const float*)d_in[20];
    const float* brS = (const float*)d_in[21];
    const float* WeS = (const float*)d_in[22];
    const float* attS = (const float*)d_in[23];
    const float* biasS = (const float*)d_in[24];
    const float* gammaS = (const float*)d_in[25];
    const float* betaS = (const float*)d_in[26];

    int n = in_sizes[0];
    int e = in_sizes[3];
    const int* src = ei;
    const int* dst = ei + e;

    float *p_xl, *p_xr;
    cudaGetSymbolAddress((void**)&p_xl, g_xl);
    cudaGetSymbolAddress((void**)&p_xr, g_xr);

    int gN = (n + 255) / 256;
    int gE = (e + 255) / 256;
    int nbScan = (n + 1023) / 1024;
    int gemmGrid = (n + 63) / 64;

    k_hist<<<gE, 256>>>(dst, e);
    k_scan1<<<nbScan, 1024>>>(n);
    k_scan23<<<gN, 256>>>(n, nbScan);
    // idx 3: layer-0 GEMM (CSR-independent) -> ncu sample window lands here
    k_gemm_l0<<<gemmGrid, 256>>>(tok, bbox, temb, bW, bb,
                                 Wl0, bl0, Wr0, br0, p_xl, p_xr, n);
    k_scatter<<<gE, 256>>>(src, dst, eattr, e);

    for (int l = 0; l < 3; l++) {
        const float *Wl, *bl, *Wr, *br, *We, *att, *bias, *gamma, *beta;
        if (l == 0) {
            Wl = Wl0; bl = bl0; Wr = Wr0; br = br0; We = We0;
            att = att0; bias = bias0; gamma = gamma0; beta = beta0;
        } else {
            int j = l - 1;
            Wl = WlS + (size_t)j * 128 * 128; bl = blS + j * 128;
            Wr = WrS + (size_t)j * 128 * 128; br = brS + j * 128;
            We = WeS + (size_t)j * 16 * 128;
            att = attS + j * 128;
            bias = biasS + j * 128; gamma = gammaS + j * 128; beta = betaS + j * 128;
        }
        if (l > 0) {
            k_gemm_tc2f<<<gemmGrid, 256>>>(Wl, bl, Wr, br, p_xl, p_xr, n, l - 1);
        }
        k_edge<<<EG, 256>>>(att, bias, relemb, We, n);
        k_bnr2<<<1, 128>>>(gamma, beta, n);
    }

    k_pool_apply<<<(n + 255) / 256, 128>>>(batch, n);
    k_pool_fin<<<(GNUM * HID + 255) / 256, 256>>>((float*)d_out);
    k_zero_tail<<<gN, 256>>>(n);
}

// round 15
// speedup vs baseline: 1.1624x; 1.0159x over previous
#include <cuda_runtime.h>
#include <cstdint>

#define NMAX 100000
#define EMAX 1600000
#define HID 128
#define GNUM 64
#define RELN 51
#define NEG 0.2f
#define EG 888   // edge-pass grid (6 * 148)

// ---------------- scratch ----------------
__device__ float g_h[(size_t)NMAX * HID];
__device__ float g_xl[(size_t)NMAX * HID];
__device__ float g_xr[(size_t)NMAX * HID];
__device__ float g_agg[(size_t)NMAX * HID];
__device__ float g_sum[256];          // BN sums/sumsqs; zero at edge launch (zero-init + bnr2 self-zero)
__device__ float g_scale[HID];
__device__ float g_shift[HID];
__device__ float g_pool[GNUM * HID];  // zero at pool launch (zero-init + tail zero)
__device__ int   g_pcnt[GNUM];
__device__ int   g_deg[NMAX];         // zero at entry (zero-init + tail zero)
__device__ int   g_rowptr[NMAX + 1];
__device__ int   g_rp2[NMAX + 1];
__device__ int   g_scan[NMAX];
__device__ int   g_bsum[128];
__device__ int   g_csr[EMAX];

// ---------------- tf32 helpers ----------------
__device__ __forceinline__ uint32_t f2tf32(float x) {
    uint32_t r;
    asm("cvt.rna.tf32.f32 %0, %1;" : "=r"(r) : "f"(x));
    return r;
}
__device__ __forceinline__ void mma_tf32(float d[4], const uint32_t a[4],
                                         const uint32_t b[2]) {
    asm volatile(
        "mma.sync.aligned.m16n8k8.row.col.f32.tf32.tf32.f32 "
        "{%0,%1,%2,%3}, {%4,%5,%6,%7}, {%8,%9}, {%0,%1,%2,%3};"
        : "+f"(d[0]), "+f"(d[1]), "+f"(d[2]), "+f"(d[3])
        : "r"(a[0]), "r"(a[1]), "r"(a[2]), "r"(a[3]), "r"(b[0]), "r"(b[1]));
}

// ---------------- CSR build ----------------
__global__ void k_hist(const int* __restrict__ dst, int e) {
    int i = blockIdx.x * blockDim.x + threadIdx.x;
    if (i < e) atomicAdd(&g_deg[dst[i]], 1);
}
__global__ void k_scan1(int n) {
    __shared__ int sh[1024];
    int t = threadIdx.x;
    int i = blockIdx.x * 1024 + t;
    int v = (i < n) ? g_deg[i] : 0;
    sh[t] = v;
    __syncthreads();
    for (int off = 1; off < 1024; off <<= 1) {
        int x = (t >= off) ? sh[t - off] : 0;
        __syncthreads();
        sh[t] += x;
        __syncthreads();
    }
    if (i < n) g_scan[i] = sh[t];
    if (t == 1023) g_bsum[blockIdx.x] = sh[1023];
}
__global__ void k_scan23(int n, int nb) {
    __shared__ int bs[128];
    int t = threadIdx.x;
    if (t < nb) bs[t] = g_bsum[t];
    __syncthreads();
    int i = blockIdx.x * blockDim.x + t;
    if (i >= n) return;
    int b = i >> 10;
    int off = 0;
    for (int j = 0; j < b; j++) off += bs[j];
    int v = g_scan[i] + off;
    g_rowptr[i + 1] = v;
    g_rp2[i + 1] = v;
    if (i == 0) { g_rowptr[0] = 0; g_rp2[0] = 0; }
}
__global__ void k_scatter(const int* __restrict__ src,
                          const int* __restrict__ dst,
                          const int* __restrict__ rel, int e) {
    int i = blockIdx.x * blockDim.x + threadIdx.x;
    if (i >= e) return;
    int d = dst[i];
    int pos = atomicAdd(&g_rp2[d], 1);
    g_csr[pos] = src[i] | (rel[i] << 20);
}
__global__ void k_zero_tail(int n) {
    int i = blockIdx.x * blockDim.x + threadIdx.x;
    if (i < n) g_deg[i] = 0;
    if (i < GNUM * HID) g_pool[i] = 0.f;
    if (i < GNUM) g_pcnt[i] = 0;
}

// ---------------- layer-0 fused dual GEMM with in-place feature build ----------------
__global__ void __launch_bounds__(256, 2)
k_gemm_l0(const int* __restrict__ tok, const float* __restrict__ bbox,
          const float* __restrict__ temb,
          const float* __restrict__ bW, const float* __restrict__ bb,
          const float* __restrict__ Wl, const float* __restrict__ bl,
          const float* __restrict__ Wr, const float* __restrict__ br,
          float* __restrict__ Yl, float* __restrict__ Yr, int n) {
    const int IND = 288, KT = 32;
    __shared__ uint32_t Xs[KT][72];
    __shared__ uint32_t Wsm[KT][264];
    int t = threadIdx.x, lane = t & 31, wid = t >> 5;
    int grp = lane >> 2, thc = lane & 3;
    int mw = wid & 1, nw = wid >> 1;
    int rowbase = blockIdx.x * 64;

    float d[2][8][4];
#pragma unroll
    for (int mi = 0; mi < 2; mi++)
#pragma unroll
        for (int nj = 0; nj < 8; nj++)
#pragma unroll
            for (int q = 0; q < 4; q++) d[mi][nj][q] = 0.f;

    int srow = t >> 2;
    int sks = (t & 3) * 8;
    int grow = rowbase + srow;
    bool rok = grow < n;
    const float* trow = &temb[(size_t)(rok ? tok[grow] : 0) * 256];
    float4 bx = make_float4(0.f, 0.f, 0.f, 0.f);
    if (rok) bx = *(const float4*)&bbox[grow * 4];

    for (int kt = 0; kt < IND; kt += KT) {
        if (kt < 256) {
#pragma unroll
            for (int q = 0; q < 2; q++) {
                float4 v = make_float4(0.f, 0.f, 0.f, 0.f);
                if (rok) v = *(const float4*)&trow[kt + sks + q * 4];
                Xs[sks + q * 4 + 0][srow] = f2tf32(v.x);
                Xs[sks + q * 4 + 1][srow] = f2tf32(v.y);
                Xs[sks + q * 4 + 2][srow] = f2tf32(v.z);
                Xs[sks + q * 4 + 3][srow] = f2tf32(v.w);
            }
        } else {
#pragma unroll
            for (int q = 0; q < 8; q++) {
                int j = sks + q;
                float v = 0.f;
                if (rok)
                    v = bb[j] + bx.x * bW[j] + bx.y * bW[32 + j] +
                        bx.z * bW[64 + j] + bx.w * bW[96 + j];
                Xs[j][srow] = f2tf32(v);
            }
        }
#pragma unroll
        for (int j = 0; j < 8; j++) {
            int id = j * 256 + t;
            int krow = id >> 6, c4 = (id & 63) * 4;
            float4 wv;
            if (c4 < 128) wv = *(const float4*)&Wl[(size_t)(kt + krow) * 128 + c4];
            else          wv = *(const float4*)&Wr[(size_t)(kt + krow) * 128 + (c4 - 128)];
            uint4 u;
            u.x = f2tf32(wv.x); u.y = f2tf32(wv.y);
            u.z = f2tf32(wv.z); u.w = f2tf32(wv.w);
            *(uint4*)&Wsm[krow][c4] = u;
        }
        __syncthreads();
#pragma unroll
        for (int kk = 0; kk < KT; kk += 8) {
            uint32_t a[2][4];
#pragma unroll
            for (int mi = 0; mi < 2; mi++) {
                int r = mw * 32 + mi * 16 + grp;
                a[mi][0] = Xs[kk + thc][r];
                a[mi][1] = Xs[kk + thc][r + 8];
                a[mi][2] = Xs[kk + thc + 4][r];
                a[mi][3] = Xs[kk + thc + 4][r + 8];
            }
            uint32_t b[8][2];
#pragma unroll
            for (int nj = 0; nj < 8; nj++) {
                int c = nw * 64 + nj * 8 + grp;
                b[nj][0] = Wsm[kk + thc][c];
                b[nj][1] = Wsm[kk + thc + 4][c];
            }
#pragma unroll
            for (int mi = 0; mi < 2; mi++)
#pragma unroll
                for (int nj = 0; nj < 8; nj++)
                    mma_tf32(d[mi][nj], a[mi], b[nj]);
        }
        __syncthreads();
    }
#pragma unroll
    for (int mi = 0; mi < 2; mi++) {
        int r0 = rowbase + mw * 32 + mi * 16 + grp;
#pragma unroll
        for (int nj = 0; nj < 8; nj++) {
            int colg = nw * 64 + nj * 8 + 2 * thc;
            const float* B = (colg < 128) ? bl : br;
            float* Y = (colg < 128) ? Yl : Yr;
            int col = colg & 127;
            float2 bv = *(const float2*)&B[col];
            if (r0 < n)
                *(float2*)&Y[(size_t)r0 * 128 + col] =
                    make_float2(d[mi][nj][0] + bv.x, d[mi][nj][1] + bv.y);
            if (r0 + 8 < n)
                *(float2*)&Y[(size_t)(r0 + 8) * 128 + col] =
                    make_float2(d[mi][nj][2] + bv.x, d[mi][nj][3] + bv.y);
        }
    }
}

// ---------------- layers 1-2 GEMM with fused BN-apply in X staging ----------------
__global__ void __launch_bounds__(256, 2)
k_gemm_tc2f(const float* __restrict__ Wl, const float* __restrict__ bl,
            const float* __restrict__ Wr, const float* __restrict__ br,
            float* __restrict__ Yl, float* __restrict__ Yr, int n, int res) {
    const int IND = 128, KT = 32;
    __shared__ uint32_t Xs[KT][72];
    __shared__ uint32_t Wsm[KT][264];
    int t = threadIdx.x, lane = t & 31, wid = t >> 5;
    int grp = lane >> 2, thc = lane & 3;
    int mw = wid & 1, nw = wid >> 1;
    int rowbase = blockIdx.x * 64;

    float d[2][8][4];
#pragma unroll
    for (int mi = 0; mi < 2; mi++)
#pragma unroll
        for (int nj = 0; nj < 8; nj++)
#pragma unroll
            for (int q = 0; q < 4; q++) d[mi][nj][q] = 0.f;

    int srow = t >> 2;
    int sks = (t & 3) * 8;
    int grow = rowbase + srow;
    bool rok = grow < n;
    size_t rowoff = (size_t)(rok ? grow : 0) * 128;

    for (int kt = 0; kt < IND; kt += KT) {
#pragma unroll
        for (int q = 0; q < 2; q++) {
            int kb = kt + sks + q * 4;
            float4 x = make_float4(0.f, 0.f, 0.f, 0.f);
            if (rok) {
                float4 v = *(const float4*)&g_agg[rowoff + kb];
                float4 s4 = *(const float4*)&g_scale[kb];
                float4 f4 = *(const float4*)&g_shift[kb];
                x.x = s4.x * v.x + f4.x;
                x.y = s4.y * v.y + f4.y;
                x.z = s4.z * v.z + f4.z;
                x.w = s4.w * v.w + f4.w;
                if (res) {
                    float4 hp = *(const float4*)&g_h[rowoff + kb];
                    x.x += hp.x; x.y += hp.y; x.z += hp.z; x.w += hp.w;
                }
                *(float4*)&g_h[rowoff + kb] = x;
            }
            Xs[sks + q * 4 + 0][srow] = f2tf32(x.x);
            Xs[sks + q * 4 + 1][srow] = f2tf32(x.y);
            Xs[sks + q * 4 + 2][srow] = f2tf32(x.z);
            Xs[sks + q * 4 + 3][srow] = f2tf32(x.w);
        }
#pragma unroll
        for (int j = 0; j < 8; j++) {
            int id = j * 256 + t;
            int krow = id >> 6, c4 = (id & 63) * 4;
            float4 wv;
            if (c4 < 128) wv = *(const float4*)&Wl[(size_t)(kt + krow) * 128 + c4];
            else          wv = *(const float4*)&Wr[(size_t)(kt + krow) * 128 + (c4 - 128)];
            uint4 u;
            u.x = f2tf32(wv.x); u.y = f2tf32(wv.y);
            u.z = f2tf32(wv.z); u.w = f2tf32(wv.w);
            *(uint4*)&Wsm[krow][c4] = u;
        }
        __syncthreads();
#pragma unroll
        for (int kk = 0; kk < KT; kk += 8) {
            uint32_t a[2][4];
#pragma unroll
            for (int mi = 0; mi < 2; mi++) {
                int r = mw * 32 + mi * 16 + grp;
                a[mi][0] = Xs[kk + thc][r];
                a[mi][1] = Xs[kk + thc][r + 8];
                a[mi][2] = Xs[kk + thc + 4][r];
                a[mi][3] = Xs[kk + thc + 4][r + 8];
            }
            uint32_t b[8][2];
#pragma unroll
            for (int nj = 0; nj < 8; nj++) {
                int c = nw * 64 + nj * 8 + grp;
                b[nj][0] = Wsm[kk + thc][c];
                b[nj][1] = Wsm[kk + thc + 4][c];
            }
#pragma unroll
            for (int mi = 0; mi < 2; mi++)
#pragma unroll
                for (int nj = 0; nj < 8; nj++)
                    mma_tf32(d[mi][nj], a[mi], b[nj]);
        }
        __syncthreads();
    }
#pragma unroll
    for (int mi = 0; mi < 2; mi++) {
        int r0 = rowbase + mw * 32 + mi * 16 + grp;
#pragma unroll
        for (int nj = 0; nj < 8; nj++) {
            int colg = nw * 64 + nj * 8 + 2 * thc;
            const float* B = (colg < 128) ? bl : br;
            float* Y = (colg < 128) ? Yl : Yr;
            int col = colg & 127;
            float2 bv = *(const float2*)&B[col];
            if (r0 < n)
                *(float2*)&Y[(size_t)r0 * 128 + col] =
                    make_float2(d[mi][nj][0] + bv.x, d[mi][nj][1] + bv.y);
            if (r0 + 8 < n)
                *(float2*)&Y[(size_t)(r0 + 8) * 128 + col] =
                    make_float2(d[mi][nj][2] + bv.x, d[mi][nj][3] + bv.y);
        }
    }
}

// ---------------- fused edge pass (unroll-2, 6 CTAs/SM) ----------------
__device__ __forceinline__ float lrelu(float m) { return fmaxf(m, NEG * m); }

__global__ void __launch_bounds__(256, 6)
k_edge(const float* __restrict__ att, const float* __restrict__ bias,
       const float* __restrict__ relemb, const float* __restrict__ We, int n) {
    __shared__ float ee[RELN * HID];
    __shared__ float red[8][32][8];
    int t = threadIdx.x;
    for (int i = t; i < RELN * HID; i += 256) {
        int r = i >> 7, j = i & 127;
        float s = 0.f;
#pragma unroll
        for (int c = 0; c < 16; c++) s += relemb[r * 16 + c] * We[c * 128 + j];
        ee[i] = s;
    }
    __syncthreads();
    int lane = t & 31, wid = t >> 5;
    float4 av = *(const float4*)&att[(lane >> 2) * 16 + (lane & 3) * 4];
    float4 bv = *(const float4*)&bias[lane * 4];
    float ps0 = 0.f, ps1 = 0.f, ps2 = 0.f, ps3 = 0.f;
    float pq0 = 0.f, pq1 = 0.f, pq2 = 0.f, pq3 = 0.f;

    for (int node = blockIdx.x * 8 + wid; node < n; node += EG * 8) {
        int r0 = g_rowptr[node], r1 = g_rowptr[node + 1];
        float4 xr = *(const float4*)&g_xr[(size_t)node * 128 + lane * 4];
        float4 acc = {0.f, 0.f, 0.f, 0.f};
        float den = 0.f;
        int i = r0;
        for (; i + 2 <= r1; i += 2) {
            int pe0 = g_csr[i], pe1 = g_csr[i + 1];
            float4 xl0 = *(const float4*)&g_xl[(size_t)(pe0 & 0xFFFFF) * 128 + lane * 4];
            float4 ev0 = *(const float4*)&ee[(pe0 >> 20) * 128 + lane * 4];
            float4 xl1 = *(const float4*)&g_xl[(size_t)(pe1 & 0xFFFFF) * 128 + lane * 4];
            float4 ev1 = *(const float4*)&ee[(pe1 >> 20) * 128 + lane * 4];
            float s0, s1;
            s0  = lrelu(xl0.x + xr.x + ev0.x) * av.x;
            s0 += lrelu(xl0.y + xr.y + ev0.y) * av.y;
            s0 += lrelu(xl0.z + xr.z + ev0.z) * av.z;
            s0 += lrelu(xl0.w + xr.w + ev0.w) * av.w;
            s1  = lrelu(xl1.x + xr.x + ev1.x) * av.x;
            s1 += lrelu(xl1.y + xr.y + ev1.y) * av.y;
            s1 += lrelu(xl1.z + xr.z + ev1.z) * av.z;
            s1 += lrelu(xl1.w + xr.w + ev1.w) * av.w;
            s0 += __shfl_xor_sync(0xffffffffu, s0, 1);
            s0 += __shfl_xor_sync(0xffffffffu, s0, 2);
            s1 += __shfl_xor_sync(0xffffffffu, s1, 1);
            s1 += __shfl_xor_sync(0xffffffffu, s1, 2);
            float p0 = __expf(s0), p1 = __expf(s1);
            den += p0 + p1;
            acc.x += p0 * xl0.x + p1 * xl1.x;
            acc.y += p0 * xl0.y + p1 * xl1.y;
            acc.z += p0 * xl0.z + p1 * xl1.z;
            acc.w += p0 * xl0.w + p1 * xl1.w;
        }
        if (i < r1) {
            int pe0 = g_csr[i];
            float4 xl0 = *(const float4*)&g_xl[(size_t)(pe0 & 0xFFFFF) * 128 + lane * 4];
            float4 ev0 = *(const float4*)&ee[(pe0 >> 20) * 128 + lane * 4];
            float s0;
            s0  = lrelu(xl0.x + xr.x + ev0.x) * av.x;
            s0 += lrelu(xl0.y + xr.y + ev0.y) * av.y;
            s0 += lrelu(xl0.z + xr.z + ev0.z) * av.z;
            s0 += lrelu(xl0.w + xr.w + ev0.w) * av.w;
            s0 += __shfl_xor_sync(0xffffffffu, s0, 1);
            s0 += __shfl_xor_sync(0xffffffffu, s0, 2);
            float p0 = __expf(s0);
            den += p0;
            acc.x += p0 * xl0.x;
            acc.y += p0 * xl0.y;
            acc.z += p0 * xl0.z;
            acc.w += p0 * xl0.w;
        }
        float inv = __frcp_rn(fmaxf(den, 1e-16f));
        float4 o;
        o.x = fmaxf(acc.x * inv + bv.x, 0.f);
        o.y = fmaxf(acc.y * inv + bv.y, 0.f);
        o.z = fmaxf(acc.z * inv + bv.z, 0.f);
        o.w = fmaxf(acc.w * inv + bv.w, 0.f);
        *(float4*)&g_agg[(size_t)node * 128 + lane * 4] = o;
        ps0 += o.x; ps1 += o.y; ps2 += o.z; ps3 += o.w;
        pq0 += o.x * o.x; pq1 += o.y * o.y; pq2 += o.z * o.z; pq3 += o.w * o.w;
    }
    red[wid][lane][0] = ps0; red[wid][lane][1] = ps1;
    red[wid][lane][2] = ps2; red[wid][lane][3] = ps3;
    red[wid][lane][4] = pq0; red[wid][lane][5] = pq1;
    red[wid][lane][6] = pq2; red[wid][lane][7] = pq3;
    __syncthreads();
    int stat = t >> 7, ch = t & 127;
    int ln = ch >> 2, j = ch & 3;
    float s = 0.f;
#pragma unroll
    for (int w = 0; w < 8; w++) s += red[w][ln][stat * 4 + j];
    atomicAdd(&g_sum[t], s);
}

// ---------------- BN finalize (trivial; self-zeroing) ----------------
__global__ void k_bnr2(const float* __restrict__ gamma,
                       const float* __restrict__ beta, int n) {
    int t = threadIdx.x;
    float s = g_sum[t];
    float q = g_sum[t + 128];
    g_sum[t] = 0.f;
    g_sum[t + 128] = 0.f;
    float inv_n = 1.0f / (float)n;
    float mu = s * inv_n;
    float var = q * inv_n - mu * mu;
    float rs = rsqrtf(var + 1e-5f);
    float sc = gamma[t] * rs;
    g_scale[t] = sc;
    g_shift[t] = beta[t] - mu * sc;
}

// ---------------- pooling (fused with final BN apply + residual) ----------------
__global__ void k_pool_apply(const int* __restrict__ batch, int n) {
    const int CHUNK = 256;
    int t = threadIdx.x;
    float sc = g_scale[t], sf = g_shift[t];
    int r0 = blockIdx.x * CHUNK;
    int rend = min(r0 + CHUNK, n);
    float a = 0.f;
    int lc = 0, cur = -1;
    for (int r = r0; r < rend; r++) {
        int g = batch[r];
        if (g != cur) {
            if (cur >= 0) {
                atomicAdd(&g_pool[cur * 128 + t], a);
                if (t == 0) atomicAdd(&g_pcnt[cur], lc);
            }
            a = 0.f;
            lc = 0;
            cur = g;
        }
        a += g_h[(size_t)r * 128 + t] + sc * g_agg[(size_t)r * 128 + t] + sf;
        lc++;
    }
    if (cur >= 0) {
        atomicAdd(&g_pool[cur * 128 + t], a);
        if (t == 0) atomicAdd(&g_pcnt[cur], lc);
    }
}
__global__ void k_pool_fin(float* __restrict__ out) {
    int i = blockIdx.x * blockDim.x + threadIdx.x;
    if (i >= GNUM * HID) return;
    out[i] = g_pool[i] / fmaxf((float)g_pcnt[i >> 7], 1.0f);
}

// ---------------- host launch ----------------
extern "C" void kernel_launch(void* const* d_in, const int* in_sizes, int n_in,
                              void* d_out, int out_size) {
    const int* tok = (const int*)d_in[0];
    const float* bbox = (const float*)d_in[1];
    const int* ei = (const int*)d_in[2];
    const int* eattr = (const int*)d_in[3];
    const int* batch = (const int*)d_in[4];
    const float* temb = (const float*)d_in[5];
    const float* bW = (const float*)d_in[6];
    const float* bb = (const float*)d_in[7];
    const float* relemb = (const float*)d_in[8];
    const float* Wl0 = (const float*)d_in[9];
    const float* bl0 = (const float*)d_in[10];
    const float* Wr0 = (const float*)d_in[11];
    const float* br0 = (const float*)d_in[12];
    const float* We0 = (const float*)d_in[13];
    const float* att0 = (const float*)d_in[14];
    const float* bias0 = (const float*)d_in[15];
    const float* gamma0 = (const float*)d_in[16];
    const float* beta0 = (const float*)d_in[17];
    const float* WlS = (const float*)d_in[18];
    const float* blS = (const float*)d_in[19];
    const float* WrS = (const float*)d_in[20];
    const float* brS = (const float*)d_in[21];
    const float* WeS = (const float*)d_in[22];
    const float* attS = (const float*)d_in[23];
    const float* biasS = (const float*)d_in[24];
    const float* gammaS = (const float*)d_in[25];
    const float* betaS = (const float*)d_in[26];

    int n = in_sizes[0];
    int e = in_sizes[3];
    const int* src = ei;
    const int* dst = ei + e;

    float *p_xl, *p_xr;
    cudaGetSymbolAddress((void**)&p_xl, g_xl);
    cudaGetSymbolAddress((void**)&p_xr, g_xr);

    int gN = (n + 255) / 256;
    int gE = (e + 255) / 256;
    int nbScan = (n + 1023) / 1024;
    int gemmGrid = (n + 63) / 64;

    k_hist<<<gE, 256>>>(dst, e);
    k_scan1<<<nbScan, 1024>>>(n);
    k_scan23<<<gN, 256>>>(n, nbScan);
    // idx 3: layer-0 GEMM (CSR-independent) -> ncu sample window lands here
    k_gemm_l0<<<gemmGrid, 256>>>(tok, bbox, temb, bW, bb,
                                 Wl0, bl0, Wr0, br0, p_xl, p_xr, n);
    k_scatter<<<gE, 256>>>(src, dst, eattr, e);

    for (int l = 0; l < 3; l++) {
        const float *Wl, *bl, *Wr, *br, *We, *att, *bias, *gamma, *beta;
        if (l == 0) {
            Wl = Wl0; bl = bl0; Wr = Wr0; br = br0; We = We0;
            att = att0; bias = bias0; gamma = gamma0; beta = beta0;
        } else {
            int j = l - 1;
            Wl = WlS + (size_t)j * 128 * 128; bl = blS + j * 128;
            Wr = WrS + (size_t)j * 128 * 128; br = brS + j * 128;
            We = WeS + (size_t)j * 16 * 128;
            att = attS + j * 128;
            bias = biasS + j * 128; gamma = gammaS + j * 128; beta = betaS + j * 128;
        }
        if (l > 0) {
            k_gemm_tc2f<<<gemmGrid, 256>>>(Wl, bl, Wr, br, p_xl, p_xr, n, l - 1);
        }
        k_edge<<<EG, 256>>>(att, bias, relemb, We, n);
        k_bnr2<<<1, 128>>>(gamma, beta, n);
    }

    k_pool_apply<<<(n + 255) / 256, 128>>>(batch, n);
    k_pool_fin<<<(GNUM * HID + 255) / 256, 256>>>((float*)d_out);
    k_zero_tail<<<gN, 256>>>(n);
}